// round 6
// baseline (speedup 1.0000x reference)
#include <cuda_runtime.h>
#include <math.h>
#include <stddef.h>

namespace {
constexpr int Bsz = 1024;
constexpr int Ssz = 64;
constexpr int Dsz = 300;
constexpr int Hsz = 512;
constexpr int Gsz = 1536;   // 3H
constexpr int Zsz = 128;
constexpr int MR  = Bsz * Ssz;   // 65536
constexpr int Rr  = 8;           // batch rows per GRU CTA
}

// Scratch (allocation-free rule: __device__ globals)
__device__ float g_GI[(size_t)2 * MR * Gsz];      // [dir][b*S + t_src][3H], ~805 MB
__device__ float g_part[(size_t)2 * Bsz * Hsz];   // masked hidden sums per direction

__device__ __forceinline__ float dot4(float4 w, float4 h, float a) {
    a = fmaf(w.x, h.x, a);
    a = fmaf(w.y, h.y, a);
    a = fmaf(w.z, h.z, a);
    a = fmaf(w.w, h.w, a);
    return a;
}

__device__ __forceinline__ float sigm(float x) {
    return 1.f / (1.f + __expf(-x));
}

// ---------------------------------------------------------------------------
// Kernel 1: GI = X @ Wih.T + bih for BOTH directions in one GEMM.
// M = B*S = 65536, N = 2*1536 = 3072 (n<1536 -> fwd weights, else bwd), K = 300.
// Tiles: BM=128, BN=64, BK=8, 256 threads, 8x4 per-thread tile.
// ---------------------------------------------------------------------------
__global__ __launch_bounds__(256) void k_gi_gemm(
    const float* __restrict__ X,
    const float* __restrict__ Wf, const float* __restrict__ bf,
    const float* __restrict__ Wb, const float* __restrict__ bb)
{
    __shared__ float As[8][128];
    __shared__ float Bs[8][64];
    const int tid = threadIdx.x;
    const int m0 = blockIdx.x * 128;
    const int n0 = blockIdx.y * 64;
    const int dir = (n0 >= Gsz) ? 1 : 0;
    const float* __restrict__ W    = dir ? Wb : Wf;
    const float* __restrict__ bias = dir ? bb : bf;
    const int g0 = n0 - dir * Gsz;

    const int tx = tid & 15;   // 16 col-groups of 4
    const int ty = tid >> 4;   // 16 row-groups of 8

    float acc[8][4];
    #pragma unroll
    for (int i = 0; i < 8; i++)
        #pragma unroll
        for (int j = 0; j < 4; j++) acc[i][j] = 0.f;

    const int arow = tid >> 1;
    const int half = tid & 1;
    const int brow = (tid & 127) >> 1;

    const float* aptr = X + (size_t)(m0 + arow) * Dsz + half * 4;
    const float* bptr = W + (size_t)(g0 + brow) * Dsz + half * 4;

    for (int k0 = 0; k0 < Dsz; k0 += 8) {
        float4 av = make_float4(0.f, 0.f, 0.f, 0.f);
        if (k0 + half * 4 < Dsz) av = *(const float4*)(aptr + k0);
        As[half*4+0][arow] = av.x;
        As[half*4+1][arow] = av.y;
        As[half*4+2][arow] = av.z;
        As[half*4+3][arow] = av.w;
        if (tid < 128) {
            float4 bv = make_float4(0.f, 0.f, 0.f, 0.f);
            if (k0 + half * 4 < Dsz) bv = *(const float4*)(bptr + k0);
            Bs[half*4+0][brow] = bv.x;
            Bs[half*4+1][brow] = bv.y;
            Bs[half*4+2][brow] = bv.z;
            Bs[half*4+3][brow] = bv.w;
        }
        __syncthreads();
        #pragma unroll
        for (int kk = 0; kk < 8; kk++) {
            float4 a0 = *(const float4*)&As[kk][ty*8];
            float4 a1 = *(const float4*)&As[kk][ty*8+4];
            float4 b  = *(const float4*)&Bs[kk][tx*4];
            float a[8] = {a0.x, a0.y, a0.z, a0.w, a1.x, a1.y, a1.z, a1.w};
            #pragma unroll
            for (int i = 0; i < 8; i++) {
                acc[i][0] = fmaf(a[i], b.x, acc[i][0]);
                acc[i][1] = fmaf(a[i], b.y, acc[i][1]);
                acc[i][2] = fmaf(a[i], b.z, acc[i][2]);
                acc[i][3] = fmaf(a[i], b.w, acc[i][3]);
            }
        }
        __syncthreads();
    }

    const float4 bv = *(const float4*)(bias + g0 + tx*4);
    #pragma unroll
    for (int i = 0; i < 8; i++) {
        size_t m = (size_t)(m0 + ty*8 + i);
        float4 o;
        o.x = acc[i][0] + bv.x;
        o.y = acc[i][1] + bv.y;
        o.z = acc[i][2] + bv.z;
        o.w = acc[i][3] + bv.w;
        *(float4*)(g_GI + ((size_t)dir * MR + m) * Gsz + g0 + tx*4) = o;
    }
}

// ---------------------------------------------------------------------------
// Kernel 2: GRU recurrence, one CTA per (direction, 8 batch rows).
// Thread tid owns hidden units j0=tid and j1=tid+256; accumulates the three
// gate dot-products (r,z,n) against smem-resident h for all 8 rows.
// Double-buffered h in smem -> one __syncthreads per step.
// Accumulates masked sum of h over steps (roll/reverse is sum-invariant).
// ---------------------------------------------------------------------------
__global__ __launch_bounds__(256) void k_gru(
    const float* __restrict__ Whh_f, const float* __restrict__ bhh_f,
    const float* __restrict__ Whh_b, const float* __restrict__ bhh_b,
    const int* __restrict__ lens)
{
    __shared__ float hsA[Rr][Hsz];
    __shared__ float hsB[Rr][Hsz];
    __shared__ int slen[Rr];

    const int tid = threadIdx.x;
    const int dir = blockIdx.y;
    const int b0 = blockIdx.x * Rr;
    const float* __restrict__ Whh = dir ? Whh_b : Whh_f;
    const float* __restrict__ bhh = dir ? bhh_b : bhh_f;
    const float* __restrict__ GIb = g_GI + (size_t)dir * MR * Gsz;

    if (tid < Rr) slen[tid] = lens[b0 + tid];
    for (int i = tid; i < Rr * Hsz; i += 256) (&hsA[0][0])[i] = 0.f;

    const int j0 = tid;
    const int j1 = tid + 256;

    const float4* __restrict__ WR0 = (const float4*)(Whh + (size_t)j0 * Hsz);
    const float4* __restrict__ WZ0 = (const float4*)(Whh + (size_t)(j0 + Hsz) * Hsz);
    const float4* __restrict__ WN0 = (const float4*)(Whh + (size_t)(j0 + 2*Hsz) * Hsz);
    const float4* __restrict__ WR1 = (const float4*)(Whh + (size_t)j1 * Hsz);
    const float4* __restrict__ WZ1 = (const float4*)(Whh + (size_t)(j1 + Hsz) * Hsz);
    const float4* __restrict__ WN1 = (const float4*)(Whh + (size_t)(j1 + 2*Hsz) * Hsz);

    const float bR0 = bhh[j0], bZ0 = bhh[j0 + Hsz], bN0 = bhh[j0 + 2*Hsz];
    const float bR1 = bhh[j1], bZ1 = bhh[j1 + Hsz], bN1 = bhh[j1 + 2*Hsz];

    float sum0[Rr], sum1[Rr];
    #pragma unroll
    for (int r = 0; r < Rr; r++) { sum0[r] = 0.f; sum1[r] = 0.f; }

    __syncthreads();

    float* hcur = &hsA[0][0];
    float* hnxt = &hsB[0][0];

    for (int t = 0; t < Ssz; t++) {
        float aR0[Rr], aZ0[Rr], aN0[Rr], aR1[Rr], aZ1[Rr], aN1[Rr];
        #pragma unroll
        for (int r = 0; r < Rr; r++) {
            aR0[r] = 0.f; aZ0[r] = 0.f; aN0[r] = 0.f;
            aR1[r] = 0.f; aZ1[r] = 0.f; aN1[r] = 0.f;
        }
        const float4* h4 = (const float4*)hcur;
        #pragma unroll 2
        for (int k4 = 0; k4 < Hsz / 4; k4++) {
            float4 wr0 = WR0[k4], wz0 = WZ0[k4], wn0 = WN0[k4];
            float4 wr1 = WR1[k4], wz1 = WZ1[k4], wn1 = WN1[k4];
            #pragma unroll
            for (int r = 0; r < Rr; r++) {
                float4 hv = h4[r * (Hsz/4) + k4];   // broadcast across warp
                aR0[r] = dot4(wr0, hv, aR0[r]);
                aZ0[r] = dot4(wz0, hv, aZ0[r]);
                aN0[r] = dot4(wn0, hv, aN0[r]);
                aR1[r] = dot4(wr1, hv, aR1[r]);
                aZ1[r] = dot4(wz1, hv, aZ1[r]);
                aN1[r] = dot4(wn1, hv, aN1[r]);
            }
        }
        const int tsrc = dir ? (Ssz - 1 - t) : t;   // backward reads reversed x
        #pragma unroll
        for (int r = 0; r < Rr; r++) {
            const float* __restrict__ gi =
                GIb + ((size_t)(b0 + r) * Ssz + tsrc) * Gsz;
            const float m = (t < slen[r]) ? 1.f : 0.f;   // forward-index mask
            {
                float rg = sigm(gi[j0]         + aR0[r] + bR0);
                float zg = sigm(gi[j0 + Hsz]   + aZ0[r] + bZ0);
                float ng = tanhf(gi[j0 + 2*Hsz] + rg * (aN0[r] + bN0));
                float hv = hcur[r * Hsz + j0];
                float hn = ng + zg * (hv - ng);    // (1-z)*n + z*h
                hnxt[r * Hsz + j0] = hn;
                sum0[r] += hn * m;
            }
            {
                float rg = sigm(gi[j1]         + aR1[r] + bR1);
                float zg = sigm(gi[j1 + Hsz]   + aZ1[r] + bZ1);
                float ng = tanhf(gi[j1 + 2*Hsz] + rg * (aN1[r] + bN1));
                float hv = hcur[r * Hsz + j1];
                float hn = ng + zg * (hv - ng);
                hnxt[r * Hsz + j1] = hn;
                sum1[r] += hn * m;
            }
        }
        __syncthreads();
        float* tp = hcur; hcur = hnxt; hnxt = tp;
    }
    #pragma unroll
    for (int r = 0; r < Rr; r++) {
        g_part[((size_t)dir * Bsz + b0 + r) * Hsz + j0] = sum0[r];
        g_part[((size_t)dir * Bsz + b0 + r) * Hsz + j1] = sum1[r];
    }
}

// ---------------------------------------------------------------------------
// Kernel 3: avg = 0.5*(sum_f + sum_b)/len; mu/sigma heads; reparam sample.
// Output layout: [final (B*Z) | mu (B*Z) | sigma (B*Z)]
// ---------------------------------------------------------------------------
__global__ __launch_bounds__(128) void k_head(
    const float* __restrict__ Wmu, const float* __restrict__ bmu,
    const float* __restrict__ Wsg, const float* __restrict__ bsg,
    const float* __restrict__ eps, const int* __restrict__ lens,
    float* __restrict__ out)
{
    __shared__ float avg[Hsz];
    const int b = blockIdx.x;
    const int tid = threadIdx.x;
    const float inv = 0.5f / (float)lens[b];   // mask.sum(0) == len (len <= S)
    for (int i = tid; i < Hsz; i += 128)
        avg[i] = (g_part[(size_t)b * Hsz + i] +
                  g_part[((size_t)Bsz + b) * Hsz + i]) * inv;
    __syncthreads();

    const float4* a4 = (const float4*)avg;
    const float4* wm = (const float4*)(Wmu + (size_t)tid * Hsz);
    const float4* ws = (const float4*)(Wsg + (size_t)tid * Hsz);
    float sm = 0.f, ss = 0.f;
    #pragma unroll 4
    for (int i = 0; i < Hsz / 4; i++) {
        float4 a = a4[i];
        sm = dot4(wm[i], a, sm);
        ss = dot4(ws[i], a, ss);
    }
    sm += bmu[tid];
    ss += bsg[tid];
    float mu = (sm >= 0.f) ? sm : 0.2f * sm;   // leaky relu 0.2
    float ls = (ss >= 0.f) ? ss : 0.2f * ss;
    float sg = expf(ls);
    float fin = fmaf(eps[(size_t)b * Zsz + tid], sg, mu);
    out[(size_t)b * Zsz + tid]              = fin;
    out[((size_t)Bsz + b) * Zsz + tid]      = mu;
    out[((size_t)2 * Bsz + b) * Zsz + tid]  = sg;
}

extern "C" void kernel_launch(void* const* d_in, const int* in_sizes, int n_in,
                              void* d_out, int out_size)
{
    const float* text  = (const float*)d_in[0];
    const int*   lens  = (const int*)  d_in[1];
    const float* Wih_f = (const float*)d_in[2];
    const float* Whh_f = (const float*)d_in[3];
    const float* bih_f = (const float*)d_in[4];
    const float* bhh_f = (const float*)d_in[5];
    const float* Wih_b = (const float*)d_in[6];
    const float* Whh_b = (const float*)d_in[7];
    const float* bih_b = (const float*)d_in[8];
    const float* bhh_b = (const float*)d_in[9];
    const float* W_mu  = (const float*)d_in[10];
    const float* b_mu  = (const float*)d_in[11];
    const float* W_sig = (const float*)d_in[12];
    const float* b_sig = (const float*)d_in[13];
    const float* eps   = (const float*)d_in[14];
    float* out = (float*)d_out;

    // 1) GI = x @ Wih.T + bih for both directions (one fused GEMM grid)
    k_gi_gemm<<<dim3(MR / 128, (2 * Gsz) / 64), 256>>>(text, Wih_f, bih_f, Wih_b, bih_b);
    // 2) GRU scan, both directions in parallel across CTAs
    k_gru<<<dim3(Bsz / Rr, 2), 256>>>(Whh_f, bhh_f, Whh_b, bhh_b, lens);
    // 3) Average + VAE heads + reparameterized sample
    k_head<<<Bsz, 128>>>(W_mu, b_mu, W_sig, b_sig, eps, lens, out);
}

// round 7
// speedup vs baseline: 2.9905x; 2.9905x over previous
#include <cuda_runtime.h>
#include <math.h>
#include <stddef.h>

namespace {
constexpr int Bsz = 1024;
constexpr int Ssz = 64;
constexpr int Dsz = 300;
constexpr int Hsz = 512;
constexpr int Gsz = 1536;   // 3H
constexpr int Zsz = 128;
constexpr int MR  = Bsz * Ssz;   // 65536
constexpr int Rr  = 8;           // batch rows per GRU CTA
}

// Scratch (allocation-free rule: __device__ globals)
__device__ float g_GI[(size_t)2 * MR * Gsz];        // [dir][b*S + t][3H]
__device__ float g_part[(size_t)2 * Bsz * Hsz];     // masked hidden sums per direction
__device__ float g_Wt[(size_t)2 * Hsz * Gsz];       // transposed Whh: [dir][k][g]
__device__ int   g_order[Bsz];                      // rows sorted by length (ascending)

__device__ __forceinline__ float dot4(float4 w, float4 h, float a) {
    a = fmaf(w.x, h.x, a);
    a = fmaf(w.y, h.y, a);
    a = fmaf(w.z, h.z, a);
    a = fmaf(w.w, h.w, a);
    return a;
}

__device__ __forceinline__ float sigm(float x) {
    return 1.f / (1.f + __expf(-x));
}

// ---------------------------------------------------------------------------
// Sort rows by length (counting sort, single block). Within-bin order is
// atomic-arrival dependent but output VALUES are permutation-invariant:
// each row's GRU result and g_part slot depend only on the row itself and
// its group's max length, which is fixed by the length multiset.
// ---------------------------------------------------------------------------
__global__ void k_sort(const int* __restrict__ lens)
{
    __shared__ int hist[Ssz + 1];
    __shared__ int off[Ssz + 2];
    const int tid = threadIdx.x;
    if (tid <= Ssz) hist[tid] = 0;
    __syncthreads();
    const int l = lens[tid];
    atomicAdd(&hist[l], 1);
    __syncthreads();
    if (tid == 0) {
        int run = 0;
        for (int i = 1; i <= Ssz; i++) { off[i] = run; run += hist[i]; }
    }
    __syncthreads();
    int pos = atomicAdd(&off[l], 1);
    g_order[pos] = tid;
}

// ---------------------------------------------------------------------------
// Transpose Whh -> Wt[dir][k][g] so GRU weight loads are coalesced.
// ---------------------------------------------------------------------------
__global__ __launch_bounds__(256) void k_wt(
    const float* __restrict__ Whh_f, const float* __restrict__ Whh_b)
{
    size_t idx = (size_t)blockIdx.x * 256 + threadIdx.x;
    const size_t per = (size_t)Hsz * Gsz;
    if (idx >= 2 * per) return;
    const int dir = (int)(idx / per);
    size_t rem = idx - (size_t)dir * per;
    const int k = (int)(rem / Gsz);
    const int g = (int)(rem % Gsz);
    const float* W = dir ? Whh_b : Whh_f;
    g_Wt[idx] = W[(size_t)g * Hsz + k];
}

// ---------------------------------------------------------------------------
// Kernel 1: GI = X @ Wih.T + bih for BOTH directions.
// M = 65536, N = 3072 (n<1536 -> fwd, else bwd), K = 300.
// 128x128x8 tiles, 256 threads, 8x8 microtile, double-buffered smem.
// ---------------------------------------------------------------------------
__global__ __launch_bounds__(256) void k_gi_gemm(
    const float* __restrict__ X,
    const float* __restrict__ Wf, const float* __restrict__ bf,
    const float* __restrict__ Wb, const float* __restrict__ bb)
{
    __shared__ float As[2][8][128];
    __shared__ float Bs[2][8][128];

    const int tid = threadIdx.x;
    const int m0 = blockIdx.x * 128;
    const int n0 = blockIdx.y * 128;
    const int dir = (n0 >= Gsz) ? 1 : 0;
    const float* __restrict__ W    = dir ? Wb : Wf;
    const float* __restrict__ bias = dir ? bb : bf;
    const int g0 = n0 - dir * Gsz;

    const int tx = tid & 15;   // n: 16 groups of 8
    const int ty = tid >> 4;   // m: 16 groups of 8

    const int arow = tid >> 1;       // 0..127
    const int half = tid & 1;        // 0/1 -> k offset 0/4

    const float* aP = X + (size_t)(m0 + arow) * Dsz + half * 4;
    const float* bP = W + (size_t)(g0 + arow) * Dsz + half * 4;

    float acc[8][8];
    #pragma unroll
    for (int i = 0; i < 8; i++)
        #pragma unroll
        for (int j = 0; j < 8; j++) acc[i][j] = 0.f;

    const int NK = (Dsz + 7) / 8;   // 38 (last tile has 4 valid k)

    // load first tile
    {
        float4 av = make_float4(0.f, 0.f, 0.f, 0.f);
        float4 bv = make_float4(0.f, 0.f, 0.f, 0.f);
        if (half * 4 < Dsz) { av = *(const float4*)aP; bv = *(const float4*)bP; }
        As[0][half*4+0][arow] = av.x; As[0][half*4+1][arow] = av.y;
        As[0][half*4+2][arow] = av.z; As[0][half*4+3][arow] = av.w;
        Bs[0][half*4+0][arow] = bv.x; Bs[0][half*4+1][arow] = bv.y;
        Bs[0][half*4+2][arow] = bv.z; Bs[0][half*4+3][arow] = bv.w;
    }
    __syncthreads();

    for (int it = 0; it < NK; it++) {
        const int buf = it & 1;
        float4 anx = make_float4(0.f, 0.f, 0.f, 0.f);
        float4 bnx = make_float4(0.f, 0.f, 0.f, 0.f);
        const bool has = (it + 1 < NK);
        if (has) {
            const int k0n = (it + 1) * 8;
            if (k0n + half * 4 < Dsz) {
                anx = *(const float4*)(aP + k0n);
                bnx = *(const float4*)(bP + k0n);
            }
        }

        #pragma unroll
        for (int kk = 0; kk < 8; kk++) {
            float4 a0 = *(const float4*)&As[buf][kk][ty*8];
            float4 a1 = *(const float4*)&As[buf][kk][ty*8+4];
            float4 b0 = *(const float4*)&Bs[buf][kk][tx*8];
            float4 b1 = *(const float4*)&Bs[buf][kk][tx*8+4];
            float a[8] = {a0.x, a0.y, a0.z, a0.w, a1.x, a1.y, a1.z, a1.w};
            float b[8] = {b0.x, b0.y, b0.z, b0.w, b1.x, b1.y, b1.z, b1.w};
            #pragma unroll
            for (int i = 0; i < 8; i++)
                #pragma unroll
                for (int j = 0; j < 8; j++)
                    acc[i][j] = fmaf(a[i], b[j], acc[i][j]);
        }

        if (has) {
            __syncthreads();
            const int nb = buf ^ 1;
            As[nb][half*4+0][arow] = anx.x; As[nb][half*4+1][arow] = anx.y;
            As[nb][half*4+2][arow] = anx.z; As[nb][half*4+3][arow] = anx.w;
            Bs[nb][half*4+0][arow] = bnx.x; Bs[nb][half*4+1][arow] = bnx.y;
            Bs[nb][half*4+2][arow] = bnx.z; Bs[nb][half*4+3][arow] = bnx.w;
            __syncthreads();
        }
    }

    const float4 bv0 = *(const float4*)(bias + g0 + tx*8);
    const float4 bv1 = *(const float4*)(bias + g0 + tx*8 + 4);
    #pragma unroll
    for (int i = 0; i < 8; i++) {
        const size_t m = (size_t)(m0 + ty*8 + i);
        float* outp = g_GI + ((size_t)dir * MR + m) * Gsz + g0 + tx*8;
        float4 o0, o1;
        o0.x = acc[i][0] + bv0.x; o0.y = acc[i][1] + bv0.y;
        o0.z = acc[i][2] + bv0.z; o0.w = acc[i][3] + bv0.w;
        o1.x = acc[i][4] + bv1.x; o1.y = acc[i][5] + bv1.y;
        o1.z = acc[i][6] + bv1.z; o1.w = acc[i][7] + bv1.w;
        *(float4*)outp       = o0;
        *(float4*)(outp + 4) = o1;
    }
}

// ---------------------------------------------------------------------------
// Kernel 2: GRU recurrence. One CTA per (direction, group of 8 length-sorted
// rows). Early exit at the group's max length (mask is t<len for BOTH dirs,
// so h after t>=len never contributes). Block index -> group rank is
// interleaved (k <-> 127-k on adjacent bids) so each SM hosts a long+short
// mix; the FFMA pipe is shared per SM, balancing makespan.
// Weights read coalesced from transposed g_Wt.
// ---------------------------------------------------------------------------
__global__ __launch_bounds__(256, 2) void k_gru(
    const float* __restrict__ bhh_f, const float* __restrict__ bhh_b,
    const int* __restrict__ lens)
{
    __shared__ float hsA[Rr][Hsz];
    __shared__ float hsB[Rr][Hsz];
    __shared__ int slen[Rr];
    __shared__ int srow[Rr];

    const int tid = threadIdx.x;
    const int dir = blockIdx.y;
    const int x = blockIdx.x;
    const int grp = (x & 1) ? (127 - (x >> 1)) : (x >> 1);   // interleave for SM balance

    const float* __restrict__ bhh = dir ? bhh_b : bhh_f;
    const float* __restrict__ GIb = g_GI + (size_t)dir * MR * Gsz;
    const float* __restrict__ WtD = g_Wt + (size_t)dir * Hsz * Gsz;

    if (tid < Rr) {
        const int b = g_order[grp * Rr + tid];
        srow[tid] = b;
        slen[tid] = lens[b];
    }
    for (int i = tid; i < Rr * Hsz; i += 256) (&hsA[0][0])[i] = 0.f;
    __syncthreads();

    int maxT = 0;
    #pragma unroll
    for (int r = 0; r < Rr; r++) maxT = max(maxT, slen[r]);

    const int j0 = tid;
    const int j1 = tid + 256;

    const float bR0 = bhh[j0], bZ0 = bhh[j0 + Hsz], bN0 = bhh[j0 + 2*Hsz];
    const float bR1 = bhh[j1], bZ1 = bhh[j1 + Hsz], bN1 = bhh[j1 + 2*Hsz];

    float sum0[Rr], sum1[Rr];
    #pragma unroll
    for (int r = 0; r < Rr; r++) { sum0[r] = 0.f; sum1[r] = 0.f; }

    float* hcur = &hsA[0][0];
    float* hnxt = &hsB[0][0];

    for (int t = 0; t < maxT; t++) {
        float aR0[Rr], aZ0[Rr], aN0[Rr], aR1[Rr], aZ1[Rr], aN1[Rr];
        #pragma unroll
        for (int r = 0; r < Rr; r++) {
            aR0[r] = 0.f; aZ0[r] = 0.f; aN0[r] = 0.f;
            aR1[r] = 0.f; aZ1[r] = 0.f; aN1[r] = 0.f;
        }

        #pragma unroll 1
        for (int k = 0; k < Hsz; k += 4) {
            #pragma unroll
            for (int kk = 0; kk < 4; kk++) {
                const float* wr = WtD + (size_t)(k + kk) * Gsz;
                const float w0r = wr[j0];
                const float w1r = wr[j1];
                const float w0z = wr[j0 + Hsz];
                const float w1z = wr[j1 + Hsz];
                const float w0n = wr[j0 + 2*Hsz];
                const float w1n = wr[j1 + 2*Hsz];
                #pragma unroll
                for (int r = 0; r < Rr; r++) {
                    const float hv = hcur[r * Hsz + k + kk];   // smem broadcast
                    aR0[r] = fmaf(w0r, hv, aR0[r]);
                    aZ0[r] = fmaf(w0z, hv, aZ0[r]);
                    aN0[r] = fmaf(w0n, hv, aN0[r]);
                    aR1[r] = fmaf(w1r, hv, aR1[r]);
                    aZ1[r] = fmaf(w1z, hv, aZ1[r]);
                    aN1[r] = fmaf(w1n, hv, aN1[r]);
                }
            }
        }

        const int tsrc = dir ? (Ssz - 1 - t) : t;   // backward reads reversed x
        #pragma unroll
        for (int r = 0; r < Rr; r++) {
            const float* __restrict__ gi =
                GIb + ((size_t)srow[r] * Ssz + tsrc) * Gsz;
            const float m = (t < slen[r]) ? 1.f : 0.f;   // forward-index mask
            {
                float rg = sigm(gi[j0]          + aR0[r] + bR0);
                float zg = sigm(gi[j0 + Hsz]    + aZ0[r] + bZ0);
                float ng = tanhf(gi[j0 + 2*Hsz] + rg * (aN0[r] + bN0));
                float hv = hcur[r * Hsz + j0];
                float hn = ng + zg * (hv - ng);    // (1-z)*n + z*h
                hnxt[r * Hsz + j0] = hn;
                sum0[r] += hn * m;
            }
            {
                float rg = sigm(gi[j1]          + aR1[r] + bR1);
                float zg = sigm(gi[j1 + Hsz]    + aZ1[r] + bZ1);
                float ng = tanhf(gi[j1 + 2*Hsz] + rg * (aN1[r] + bN1));
                float hv = hcur[r * Hsz + j1];
                float hn = ng + zg * (hv - ng);
                hnxt[r * Hsz + j1] = hn;
                sum1[r] += hn * m;
            }
        }
        __syncthreads();
        float* tp = hcur; hcur = hnxt; hnxt = tp;
    }

    #pragma unroll
    for (int r = 0; r < Rr; r++) {
        g_part[((size_t)dir * Bsz + srow[r]) * Hsz + j0] = sum0[r];
        g_part[((size_t)dir * Bsz + srow[r]) * Hsz + j1] = sum1[r];
    }
}

// ---------------------------------------------------------------------------
// Kernel 3: avg = 0.5*(sum_f + sum_b)/len; mu/sigma heads; reparam sample.
// Output layout: [final (B*Z) | mu (B*Z) | sigma (B*Z)]
// ---------------------------------------------------------------------------
__global__ __launch_bounds__(128) void k_head(
    const float* __restrict__ Wmu, const float* __restrict__ bmu,
    const float* __restrict__ Wsg, const float* __restrict__ bsg,
    const float* __restrict__ eps, const int* __restrict__ lens,
    float* __restrict__ out)
{
    __shared__ float avg[Hsz];
    const int b = blockIdx.x;
    const int tid = threadIdx.x;
    const float inv = 0.5f / (float)lens[b];   // mask.sum(0) == len
    for (int i = tid; i < Hsz; i += 128)
        avg[i] = (g_part[(size_t)b * Hsz + i] +
                  g_part[((size_t)Bsz + b) * Hsz + i]) * inv;
    __syncthreads();

    const float4* a4 = (const float4*)avg;
    const float4* wm = (const float4*)(Wmu + (size_t)tid * Hsz);
    const float4* ws = (const float4*)(Wsg + (size_t)tid * Hsz);
    float sm = 0.f, ss = 0.f;
    #pragma unroll 4
    for (int i = 0; i < Hsz / 4; i++) {
        float4 a = a4[i];
        sm = dot4(wm[i], a, sm);
        ss = dot4(ws[i], a, ss);
    }
    sm += bmu[tid];
    ss += bsg[tid];
    float mu = (sm >= 0.f) ? sm : 0.2f * sm;   // leaky relu 0.2
    float ls = (ss >= 0.f) ? ss : 0.2f * ss;
    float sg = expf(ls);
    float fin = fmaf(eps[(size_t)b * Zsz + tid], sg, mu);
    out[(size_t)b * Zsz + tid]              = fin;
    out[((size_t)Bsz + b) * Zsz + tid]      = mu;
    out[((size_t)2 * Bsz + b) * Zsz + tid]  = sg;
}

extern "C" void kernel_launch(void* const* d_in, const int* in_sizes, int n_in,
                              void* d_out, int out_size)
{
    const float* text  = (const float*)d_in[0];
    const int*   lens  = (const int*)  d_in[1];
    const float* Wih_f = (const float*)d_in[2];
    const float* Whh_f = (const float*)d_in[3];
    const float* bih_f = (const float*)d_in[4];
    const float* bhh_f = (const float*)d_in[5];
    const float* Wih_b = (const float*)d_in[6];
    const float* Whh_b = (const float*)d_in[7];
    const float* bih_b = (const float*)d_in[8];
    const float* bhh_b = (const float*)d_in[9];
    const float* W_mu  = (const float*)d_in[10];
    const float* b_mu  = (const float*)d_in[11];
    const float* W_sig = (const float*)d_in[12];
    const float* b_sig = (const float*)d_in[13];
    const float* eps   = (const float*)d_in[14];
    float* out = (float*)d_out;

    // 0) length sort + weight transpose (cheap, parallel with nothing)
    k_sort<<<1, Bsz>>>(lens);
    {
        const size_t total = (size_t)2 * Hsz * Gsz;
        k_wt<<<(unsigned)((total + 255) / 256), 256>>>(Whh_f, Whh_b);
    }
    // 1) GI = x @ Wih.T + bih, both directions fused
    k_gi_gemm<<<dim3(MR / 128, (2 * Gsz) / 128), 256>>>(text, Wih_f, bih_f, Wih_b, bih_b);
    // 2) GRU scan (length-sorted groups, early exit, balanced placement)
    k_gru<<<dim3(Bsz / Rr, 2), 256>>>(bhh_f, bhh_b, lens);
    // 3) Average + VAE heads + reparameterized sample
    k_head<<<Bsz, 128>>>(W_mu, b_mu, W_sig, b_sig, eps, lens, out);
}

// round 8
// speedup vs baseline: 3.6789x; 1.2302x over previous
#include <cuda_runtime.h>
#include <math.h>
#include <stddef.h>

namespace {
constexpr int Bsz = 1024;
constexpr int Ssz = 64;
constexpr int Dsz = 300;
constexpr int Hsz = 512;
constexpr int Gsz = 1536;   // 3H
constexpr int Zsz = 128;
constexpr int MR  = Bsz * Ssz;   // 65536
constexpr int Rr  = 8;           // batch rows per GRU CTA (4 f32x2 pairs)
}

typedef unsigned long long ull;

// Scratch (allocation-free rule: __device__ globals)
__device__ float g_GI[(size_t)2 * MR * Gsz];        // [dir][b*S + t][3H]
__device__ float g_part[(size_t)2 * Bsz * Hsz];     // masked hidden sums per direction
__device__ float g_W4[(size_t)2 * (Hsz/4) * Gsz * 4]; // packed Whh: [dir][k/4][g][kk]
__device__ int   g_order[Bsz];                      // rows sorted by length (ascending)

// packed f32x2 helpers (FFMA2 — 2 exact fp32 FMAs per instruction)
#define FMA2(acc, a, b) \
    asm("fma.rn.f32x2 %0, %1, %2, %0;" : "+l"(acc) : "l"(a), "l"(b))
#define PACK2(d, s) \
    asm("mov.b64 %0, {%1, %1};" : "=l"(d) : "f"(s))

__device__ __forceinline__ float f2lo(ull u) { return __uint_as_float((unsigned)u); }
__device__ __forceinline__ float f2hi(ull u) { return __uint_as_float((unsigned)(u >> 32)); }

__device__ __forceinline__ float dot4(float4 w, float4 h, float a) {
    a = fmaf(w.x, h.x, a);
    a = fmaf(w.y, h.y, a);
    a = fmaf(w.z, h.z, a);
    a = fmaf(w.w, h.w, a);
    return a;
}

__device__ __forceinline__ float sigm(float x) {
    return 1.f / (1.f + __expf(-x));
}

// ---------------------------------------------------------------------------
// Sort rows by length (counting sort, single block). Output values are
// permutation-invariant within equal-length bins.
// ---------------------------------------------------------------------------
__global__ void k_sort(const int* __restrict__ lens)
{
    __shared__ int hist[Ssz + 1];
    __shared__ int off[Ssz + 2];
    const int tid = threadIdx.x;
    if (tid <= Ssz) hist[tid] = 0;
    __syncthreads();
    const int l = lens[tid];
    atomicAdd(&hist[l], 1);
    __syncthreads();
    if (tid == 0) {
        int run = 0;
        for (int i = 1; i <= Ssz; i++) { off[i] = run; run += hist[i]; }
    }
    __syncthreads();
    int pos = atomicAdd(&off[l], 1);
    g_order[pos] = tid;
}

// ---------------------------------------------------------------------------
// Repack Whh -> W4[dir][k/4][g][kk]: one LDG.128 delivers 4 consecutive-k
// weights for one gate column g. Coalesced GRU reads.
// ---------------------------------------------------------------------------
__global__ __launch_bounds__(256) void k_wt4(
    const float* __restrict__ Whh_f, const float* __restrict__ Whh_b)
{
    size_t idx = (size_t)blockIdx.x * 256 + threadIdx.x;
    const size_t per = (size_t)(Hsz/4) * Gsz * 4;
    if (idx >= 2 * per) return;
    const int dir = (int)(idx / per);
    size_t rem = idx - (size_t)dir * per;
    const int kk = (int)(rem & 3);
    size_t r2 = rem >> 2;
    const int g  = (int)(r2 % Gsz);
    const int k4 = (int)(r2 / Gsz);
    const float* W = dir ? Whh_b : Whh_f;
    g_W4[idx] = W[(size_t)g * Hsz + k4 * 4 + kk];
}

// ---------------------------------------------------------------------------
// Kernel 1: GI = X @ Wih.T + bih for BOTH directions, f32x2 packed.
// M = 65536, N = 3072, K = 300. 128x128x8 tiles, 256 threads, 8x8 microtile
// (8 m-rows x 4 n-pairs), double-buffered smem.
// ---------------------------------------------------------------------------
__global__ __launch_bounds__(256) void k_gi_gemm(
    const float* __restrict__ X,
    const float* __restrict__ Wf, const float* __restrict__ bf,
    const float* __restrict__ Wb, const float* __restrict__ bb)
{
    __shared__ __align__(16) float As[2][8][128];
    __shared__ __align__(16) float Bs[2][8][128];

    const int tid = threadIdx.x;
    const int m0 = blockIdx.x * 128;
    const int n0 = blockIdx.y * 128;
    const int dir = (n0 >= Gsz) ? 1 : 0;
    const float* __restrict__ W    = dir ? Wb : Wf;
    const float* __restrict__ bias = dir ? bb : bf;
    const int g0 = n0 - dir * Gsz;

    const int tx = tid & 15;   // n: 16 groups of 8
    const int ty = tid >> 4;   // m: 16 groups of 8

    const int arow = tid >> 1;       // 0..127
    const int half = tid & 1;        // 0/1 -> k offset 0/4

    const float* aP = X + (size_t)(m0 + arow) * Dsz + half * 4;
    const float* bP = W + (size_t)(g0 + arow) * Dsz + half * 4;

    ull acc2[8][4];
    #pragma unroll
    for (int i = 0; i < 8; i++)
        #pragma unroll
        for (int j = 0; j < 4; j++) acc2[i][j] = 0ULL;   // (0.0f, 0.0f)

    const int NK = (Dsz + 7) / 8;   // 38 (last tile has 4 valid k)

    {
        float4 av = make_float4(0.f, 0.f, 0.f, 0.f);
        float4 bv = make_float4(0.f, 0.f, 0.f, 0.f);
        if (half * 4 < Dsz) { av = *(const float4*)aP; bv = *(const float4*)bP; }
        As[0][half*4+0][arow] = av.x; As[0][half*4+1][arow] = av.y;
        As[0][half*4+2][arow] = av.z; As[0][half*4+3][arow] = av.w;
        Bs[0][half*4+0][arow] = bv.x; Bs[0][half*4+1][arow] = bv.y;
        Bs[0][half*4+2][arow] = bv.z; Bs[0][half*4+3][arow] = bv.w;
    }
    __syncthreads();

    for (int it = 0; it < NK; it++) {
        const int buf = it & 1;
        float4 anx = make_float4(0.f, 0.f, 0.f, 0.f);
        float4 bnx = make_float4(0.f, 0.f, 0.f, 0.f);
        const bool has = (it + 1 < NK);
        if (has) {
            const int k0n = (it + 1) * 8;
            if (k0n + half * 4 < Dsz) {
                anx = *(const float4*)(aP + k0n);
                bnx = *(const float4*)(bP + k0n);
            }
        }

        #pragma unroll
        for (int kk = 0; kk < 8; kk++) {
            float4 a0 = *(const float4*)&As[buf][kk][ty*8];
            float4 a1 = *(const float4*)&As[buf][kk][ty*8+4];
            const double2* bd = (const double2*)&Bs[buf][kk][0];
            double2 b01 = bd[tx*2];
            double2 b23 = bd[tx*2+1];
            ull bb2[4] = { __double_as_longlong(b01.x), __double_as_longlong(b01.y),
                           __double_as_longlong(b23.x), __double_as_longlong(b23.y) };
            float a[8] = {a0.x, a0.y, a0.z, a0.w, a1.x, a1.y, a1.z, a1.w};
            #pragma unroll
            for (int i = 0; i < 8; i++) {
                ull ad; PACK2(ad, a[i]);
                #pragma unroll
                for (int j = 0; j < 4; j++)
                    FMA2(acc2[i][j], ad, bb2[j]);
            }
        }

        if (has) {
            __syncthreads();
            const int nb = buf ^ 1;
            As[nb][half*4+0][arow] = anx.x; As[nb][half*4+1][arow] = anx.y;
            As[nb][half*4+2][arow] = anx.z; As[nb][half*4+3][arow] = anx.w;
            Bs[nb][half*4+0][arow] = bnx.x; Bs[nb][half*4+1][arow] = bnx.y;
            Bs[nb][half*4+2][arow] = bnx.z; Bs[nb][half*4+3][arow] = bnx.w;
            __syncthreads();
        }
    }

    const float4 bv0 = *(const float4*)(bias + g0 + tx*8);
    const float4 bv1 = *(const float4*)(bias + g0 + tx*8 + 4);
    const float bb8[8] = {bv0.x, bv0.y, bv0.z, bv0.w, bv1.x, bv1.y, bv1.z, bv1.w};
    #pragma unroll
    for (int i = 0; i < 8; i++) {
        const size_t m = (size_t)(m0 + ty*8 + i);
        float* outp = g_GI + ((size_t)dir * MR + m) * Gsz + g0 + tx*8;
        float o[8];
        #pragma unroll
        for (int j = 0; j < 4; j++) {
            o[2*j]   = f2lo(acc2[i][j]) + bb8[2*j];
            o[2*j+1] = f2hi(acc2[i][j]) + bb8[2*j+1];
        }
        *(float4*)outp       = make_float4(o[0], o[1], o[2], o[3]);
        *(float4*)(outp + 4) = make_float4(o[4], o[5], o[6], o[7]);
    }
}

// ---------------------------------------------------------------------------
// Kernel 2: GRU recurrence, f32x2 packed over row pairs.
// One CTA per (direction, group of 8 length-sorted rows); early exit at the
// group max length; long/short CTAs interleaved so each SM hosts a balanced
// pair. h stored as row-pair float2 in smem; weights from packed g_W4.
// ---------------------------------------------------------------------------
__global__ __launch_bounds__(256, 2) void k_gru(
    const float* __restrict__ bhh_f, const float* __restrict__ bhh_b,
    const int* __restrict__ lens)
{
    // h layout: [pair(4)][k(512)] x float2(row2p, row2p+1) = 16 KB per buffer
    __shared__ __align__(16) float hsA[4 * Hsz * 2];
    __shared__ __align__(16) float hsB[4 * Hsz * 2];
    __shared__ int slen[Rr];
    __shared__ int srow[Rr];

    const int tid = threadIdx.x;
    const int dir = blockIdx.y;
    const int x = blockIdx.x;
    const int grp = (x & 1) ? (127 - (x >> 1)) : (x >> 1);   // long/short interleave

    const float* __restrict__ bhh = dir ? bhh_b : bhh_f;
    const float* __restrict__ GIb = g_GI + (size_t)dir * MR * Gsz;
    const float4* __restrict__ W4D =
        (const float4*)g_W4 + (size_t)dir * (Hsz/4) * Gsz;

    if (tid < Rr) {
        const int b = g_order[grp * Rr + tid];
        srow[tid] = b;
        slen[tid] = lens[b];
    }
    for (int i = tid; i < 4 * Hsz * 2; i += 256) { hsA[i] = 0.f; }
    __syncthreads();

    int maxT = 0;
    #pragma unroll
    for (int r = 0; r < Rr; r++) maxT = max(maxT, slen[r]);

    const int j0 = tid;
    const int j1 = tid + 256;

    const float bR0 = bhh[j0], bZ0 = bhh[j0 + Hsz], bN0 = bhh[j0 + 2*Hsz];
    const float bR1 = bhh[j1], bZ1 = bhh[j1 + Hsz], bN1 = bhh[j1 + 2*Hsz];

    float sum0[Rr], sum1[Rr];
    #pragma unroll
    for (int r = 0; r < Rr; r++) { sum0[r] = 0.f; sum1[r] = 0.f; }

    float* hcur = hsA;
    float* hnxt = hsB;

    for (int t = 0; t < maxT; t++) {
        ull aR0[4], aZ0[4], aN0[4], aR1[4], aZ1[4], aN1[4];
        #pragma unroll
        for (int p = 0; p < 4; p++) {
            aR0[p] = 0ULL; aZ0[p] = 0ULL; aN0[p] = 0ULL;
            aR1[p] = 0ULL; aZ1[p] = 0ULL; aN1[p] = 0ULL;
        }

        const double2* hb = (const double2*)hcur;   // [pair*256 + k/2]

        #pragma unroll 1
        for (int k4 = 0; k4 < Hsz / 4; k4++) {
            const size_t base = (size_t)k4 * Gsz;
            const float4 vr0 = W4D[base + j0];
            const float4 vz0 = W4D[base + j0 + Hsz];
            const float4 vn0 = W4D[base + j0 + 2*Hsz];
            const float4 vr1 = W4D[base + j1];
            const float4 vz1 = W4D[base + j1 + Hsz];
            const float4 vn1 = W4D[base + j1 + 2*Hsz];

            ull h0[4], h1[4], h2[4], h3[4];
            #pragma unroll
            for (int p = 0; p < 4; p++) {
                double2 dA = hb[p * 256 + 2*k4];
                double2 dB = hb[p * 256 + 2*k4 + 1];
                h0[p] = __double_as_longlong(dA.x);
                h1[p] = __double_as_longlong(dA.y);
                h2[p] = __double_as_longlong(dB.x);
                h3[p] = __double_as_longlong(dB.y);
            }

#define DOKK(C, HARR) do {                                                     \
    ull w0r, w0z, w0n, w1r, w1z, w1n;                                          \
    PACK2(w0r, vr0.C); PACK2(w0z, vz0.C); PACK2(w0n, vn0.C);                   \
    PACK2(w1r, vr1.C); PACK2(w1z, vz1.C); PACK2(w1n, vn1.C);                   \
    _Pragma("unroll")                                                          \
    for (int p = 0; p < 4; p++) {                                              \
        FMA2(aR0[p], w0r, HARR[p]); FMA2(aZ0[p], w0z, HARR[p]);                \
        FMA2(aN0[p], w0n, HARR[p]);                                            \
        FMA2(aR1[p], w1r, HARR[p]); FMA2(aZ1[p], w1z, HARR[p]);                \
        FMA2(aN1[p], w1n, HARR[p]);                                            \
    } } while (0)

            DOKK(x, h0);
            DOKK(y, h1);
            DOKK(z, h2);
            DOKK(w, h3);
#undef DOKK
        }

        const int tsrc = dir ? (Ssz - 1 - t) : t;   // backward reads reversed x
        #pragma unroll
        for (int r = 0; r < Rr; r++) {
            const int p = r >> 1;
            const int c = r & 1;
            const float* __restrict__ gi =
                GIb + ((size_t)srow[r] * Ssz + tsrc) * Gsz;
            const float m = (t < slen[r]) ? 1.f : 0.f;   // forward-index mask
            {
                const float aR = c ? f2hi(aR0[p]) : f2lo(aR0[p]);
                const float aZ = c ? f2hi(aZ0[p]) : f2lo(aZ0[p]);
                const float aN = c ? f2hi(aN0[p]) : f2lo(aN0[p]);
                float rg = sigm(gi[j0]          + aR + bR0);
                float zg = sigm(gi[j0 + Hsz]    + aZ + bZ0);
                float ng = tanhf(gi[j0 + 2*Hsz] + rg * (aN + bN0));
                float hv = hcur[(p * Hsz + j0) * 2 + c];
                float hn = ng + zg * (hv - ng);    // (1-z)*n + z*h
                hnxt[(p * Hsz + j0) * 2 + c] = hn;
                sum0[r] += hn * m;
            }
            {
                const float aR = c ? f2hi(aR1[p]) : f2lo(aR1[p]);
                const float aZ = c ? f2hi(aZ1[p]) : f2lo(aZ1[p]);
                const float aN = c ? f2hi(aN1[p]) : f2lo(aN1[p]);
                float rg = sigm(gi[j1]          + aR + bR1);
                float zg = sigm(gi[j1 + Hsz]    + aZ + bZ1);
                float ng = tanhf(gi[j1 + 2*Hsz] + rg * (aN + bN1));
                float hv = hcur[(p * Hsz + j1) * 2 + c];
                float hn = ng + zg * (hv - ng);
                hnxt[(p * Hsz + j1) * 2 + c] = hn;
                sum1[r] += hn * m;
            }
        }
        __syncthreads();
        float* tp = hcur; hcur = hnxt; hnxt = tp;
    }

    #pragma unroll
    for (int r = 0; r < Rr; r++) {
        g_part[((size_t)dir * Bsz + srow[r]) * Hsz + j0] = sum0[r];
        g_part[((size_t)dir * Bsz + srow[r]) * Hsz + j1] = sum1[r];
    }
}

// ---------------------------------------------------------------------------
// Kernel 3: avg = 0.5*(sum_f + sum_b)/len; mu/sigma heads; reparam sample.
// Output layout: [final (B*Z) | mu (B*Z) | sigma (B*Z)]
// ---------------------------------------------------------------------------
__global__ __launch_bounds__(128) void k_head(
    const float* __restrict__ Wmu, const float* __restrict__ bmu,
    const float* __restrict__ Wsg, const float* __restrict__ bsg,
    const float* __restrict__ eps, const int* __restrict__ lens,
    float* __restrict__ out)
{
    __shared__ float avg[Hsz];
    const int b = blockIdx.x;
    const int tid = threadIdx.x;
    const float inv = 0.5f / (float)lens[b];   // mask.sum(0) == len
    for (int i = tid; i < Hsz; i += 128)
        avg[i] = (g_part[(size_t)b * Hsz + i] +
                  g_part[((size_t)Bsz + b) * Hsz + i]) * inv;
    __syncthreads();

    const float4* a4 = (const float4*)avg;
    const float4* wm = (const float4*)(Wmu + (size_t)tid * Hsz);
    const float4* ws = (const float4*)(Wsg + (size_t)tid * Hsz);
    float sm = 0.f, ss = 0.f;
    #pragma unroll 4
    for (int i = 0; i < Hsz / 4; i++) {
        float4 a = a4[i];
        sm = dot4(wm[i], a, sm);
        ss = dot4(ws[i], a, ss);
    }
    sm += bmu[tid];
    ss += bsg[tid];
    float mu = (sm >= 0.f) ? sm : 0.2f * sm;   // leaky relu 0.2
    float ls = (ss >= 0.f) ? ss : 0.2f * ss;
    float sg = expf(ls);
    float fin = fmaf(eps[(size_t)b * Zsz + tid], sg, mu);
    out[(size_t)b * Zsz + tid]              = fin;
    out[((size_t)Bsz + b) * Zsz + tid]      = mu;
    out[((size_t)2 * Bsz + b) * Zsz + tid]  = sg;
}

extern "C" void kernel_launch(void* const* d_in, const int* in_sizes, int n_in,
                              void* d_out, int out_size)
{
    const float* text  = (const float*)d_in[0];
    const int*   lens  = (const int*)  d_in[1];
    const float* Wih_f = (const float*)d_in[2];
    const float* Whh_f = (const float*)d_in[3];
    const float* bih_f = (const float*)d_in[4];
    const float* bhh_f = (const float*)d_in[5];
    const float* Wih_b = (const float*)d_in[6];
    const float* Whh_b = (const float*)d_in[7];
    const float* bih_b = (const float*)d_in[8];
    const float* bhh_b = (const float*)d_in[9];
    const float* W_mu  = (const float*)d_in[10];
    const float* b_mu  = (const float*)d_in[11];
    const float* W_sig = (const float*)d_in[12];
    const float* b_sig = (const float*)d_in[13];
    const float* eps   = (const float*)d_in[14];
    float* out = (float*)d_out;

    // 0) length sort + packed weight layout (one-time, cheap)
    k_sort<<<1, Bsz>>>(lens);
    {
        const size_t total = (size_t)2 * (Hsz/4) * Gsz * 4;
        k_wt4<<<(unsigned)((total + 255) / 256), 256>>>(Whh_f, Whh_b);
    }
    // 1) GI = x @ Wih.T + bih, both directions fused, f32x2
    k_gi_gemm<<<dim3(MR / 128, (2 * Gsz) / 128), 256>>>(text, Wih_f, bih_f, Wih_b, bih_b);
    // 2) GRU scan (sorted groups, early exit, balanced placement, f32x2)
    k_gru<<<dim3(Bsz / Rr, 2), 256>>>(bhh_f, bhh_b, lens);
    // 3) Average + VAE heads + reparameterized sample
    k_head<<<Bsz, 128>>>(W_mu, b_mu, W_sig, b_sig, eps, lens, out);
}

// round 9
// speedup vs baseline: 4.6424x; 1.2619x over previous
#include <cuda_runtime.h>
#include <math.h>
#include <stddef.h>
#include <stdint.h>

namespace {
constexpr int Bsz = 1024;
constexpr int Ssz = 64;
constexpr int Dsz = 300;
constexpr int Hsz = 512;
constexpr int Gsz = 1536;   // 3H
constexpr int Zsz = 128;
constexpr int MR  = Bsz * Ssz;   // 65536
constexpr int Rr  = 8;           // batch rows per GRU CTA (4 f32x2 pairs)

constexpr int NST    = 3;                       // weight pipeline stages
constexpr int WBYTES = Gsz * 4 * 4;             // 24576 B per k4 slab
constexpr int OFF_W    = 0;
constexpr int OFF_HA   = NST * WBYTES;          // 73728
constexpr int OFF_HB   = OFF_HA + Rr * Hsz * 4; // +16384
constexpr int OFF_MB   = OFF_HB + Rr * Hsz * 4; // +16384 -> 106496 (8-aligned)
constexpr int OFF_SLEN = OFF_MB + NST * 8;
constexpr int OFF_SROW = OFF_SLEN + Rr * 4;
constexpr int SMEM_GRU = OFF_SROW + Rr * 4 + 64;
}

typedef unsigned long long ull;

// Scratch (allocation-free rule: __device__ globals)
__device__ float g_GI[(size_t)2 * MR * Gsz];          // [dir][t][sorted_b][3H]
__device__ float g_part[(size_t)2 * Bsz * Hsz];       // masked hidden sums per direction
__device__ float g_W4[(size_t)2 * (Hsz/4) * Gsz * 4]; // packed Whh: [dir][k/4][g][kk]
__device__ int   g_order[Bsz];                        // rows sorted by length (ascending)

// packed f32x2 helpers (FFMA2 — 2 exact fp32 FMAs per instruction)
#define FMA2(acc, a, b) \
    asm("fma.rn.f32x2 %0, %1, %2, %0;" : "+l"(acc) : "l"(a), "l"(b))
#define PACK2(d, s) \
    asm("mov.b64 %0, {%1, %1};" : "=l"(d) : "f"(s))

__device__ __forceinline__ float f2lo(ull u) { return __uint_as_float((unsigned)u); }
__device__ __forceinline__ float f2hi(ull u) { return __uint_as_float((unsigned)(u >> 32)); }

__device__ __forceinline__ uint32_t smem_u32(const void* p) {
    return (uint32_t)__cvta_generic_to_shared(p);
}

__device__ __forceinline__ void mbar_init(uint32_t mbar, uint32_t cnt) {
    asm volatile("mbarrier.init.shared.b64 [%0], %1;" :: "r"(mbar), "r"(cnt) : "memory");
}
__device__ __forceinline__ void mbar_expect_tx(uint32_t mbar, uint32_t bytes) {
    asm volatile("mbarrier.arrive.expect_tx.shared.b64 _, [%0], %1;"
                 :: "r"(mbar), "r"(bytes) : "memory");
}
__device__ __forceinline__ void mbar_wait(uint32_t mbar, uint32_t phase) {
    uint32_t done;
    asm volatile("{\n\t.reg .pred p;\n\t"
        "mbarrier.try_wait.parity.acquire.cta.shared::cta.b64 p, [%1], %2;\n\t"
        "selp.b32 %0, 1, 0, p;\n\t}"
        : "=r"(done) : "r"(mbar), "r"(phase) : "memory");
    while (!done) {
        asm volatile("{\n\t.reg .pred p;\n\t"
            "mbarrier.try_wait.parity.acquire.cta.shared::cta.b64 p, [%1], %2, 0x989680;\n\t"
            "selp.b32 %0, 1, 0, p;\n\t}"
            : "=r"(done) : "r"(mbar), "r"(phase) : "memory");
    }
}
__device__ __forceinline__ void bulk_g2s(uint32_t dst, const void* src,
                                         uint32_t bytes, uint32_t mbar) {
    asm volatile(
        "cp.async.bulk.shared::cluster.global.mbarrier::complete_tx::bytes "
        "[%0], [%1], %2, [%3];"
        :: "r"(dst), "l"(src), "r"(bytes), "r"(mbar) : "memory");
}

__device__ __forceinline__ float dot4(float4 w, float4 h, float a) {
    a = fmaf(w.x, h.x, a);
    a = fmaf(w.y, h.y, a);
    a = fmaf(w.z, h.z, a);
    a = fmaf(w.w, h.w, a);
    return a;
}

__device__ __forceinline__ float sigm(float x) {
    return 1.f / (1.f + __expf(-x));
}

// ---------------------------------------------------------------------------
// Sort rows by length (counting sort, single block). Output values are
// permutation-invariant within equal-length bins.
// ---------------------------------------------------------------------------
__global__ void k_sort(const int* __restrict__ lens)
{
    __shared__ int hist[Ssz + 1];
    __shared__ int off[Ssz + 2];
    const int tid = threadIdx.x;
    if (tid <= Ssz) hist[tid] = 0;
    __syncthreads();
    const int l = lens[tid];
    atomicAdd(&hist[l], 1);
    __syncthreads();
    if (tid == 0) {
        int run = 0;
        for (int i = 1; i <= Ssz; i++) { off[i] = run; run += hist[i]; }
    }
    __syncthreads();
    int pos = atomicAdd(&off[l], 1);
    g_order[pos] = tid;
}

// ---------------------------------------------------------------------------
// Repack Whh -> W4[dir][k/4][g][kk]
// ---------------------------------------------------------------------------
__global__ __launch_bounds__(256) void k_wt4(
    const float* __restrict__ Whh_f, const float* __restrict__ Whh_b)
{
    size_t idx = (size_t)blockIdx.x * 256 + threadIdx.x;
    const size_t per = (size_t)(Hsz/4) * Gsz * 4;
    if (idx >= 2 * per) return;
    const int dir = (int)(idx / per);
    size_t rem = idx - (size_t)dir * per;
    const int kk = (int)(rem & 3);
    size_t r2 = rem >> 2;
    const int g  = (int)(r2 % Gsz);
    const int k4 = (int)(r2 / Gsz);
    const float* W = dir ? Whh_b : Whh_f;
    g_W4[idx] = W[(size_t)g * Hsz + k4 * 4 + kk];
}

// ---------------------------------------------------------------------------
// Kernel 1: GI[dir][t][sorted_b][g] = x[order(sb)][dir? 63-t : t] @ Wih.T + b.
// t-major layout over length-sorted rows; tiles with t >= chunk-max-length
// exit immediately (those GI values are never read by the GRU).
// 128x128x8 tiles, 256 threads, 8x8 microtile (f32x2), double-buffered smem.
// grid.x = chunk(8) * 64 t-values; grid.y = 24 n-tiles (both dirs).
// ---------------------------------------------------------------------------
__global__ __launch_bounds__(256) void k_gi_gemm(
    const float* __restrict__ X,
    const float* __restrict__ Wf, const float* __restrict__ bf,
    const float* __restrict__ Wb, const float* __restrict__ bb,
    const int* __restrict__ lens)
{
    __shared__ __align__(16) float As[2][8][128];
    __shared__ __align__(16) float Bs[2][8][128];

    const int bx = blockIdx.x;
    const int chunk = bx >> 6;
    const int t = bx & 63;

    // skip: GI only read for t < max len over this sorted 128-row chunk
    if (t >= lens[g_order[chunk * 128 + 127]]) return;

    const int tid = threadIdx.x;
    const int n0 = blockIdx.y * 128;
    const int dir = (n0 >= Gsz) ? 1 : 0;
    const float* __restrict__ W    = dir ? Wb : Wf;
    const float* __restrict__ bias = dir ? bb : bf;
    const int g0 = n0 - dir * Gsz;
    const int s  = dir ? (Ssz - 1 - t) : t;     // backward pre-reads reversed x

    const int tx = tid & 15;
    const int ty = tid >> 4;

    const int arow = tid >> 1;       // 0..127
    const int half = tid & 1;        // 0/1 -> k offset 0/4

    const int browB = g_order[chunk * 128 + arow];
    const float* aP = X + ((size_t)browB * Ssz + s) * Dsz + half * 4;
    const float* bP = W + (size_t)(g0 + arow) * Dsz + half * 4;

    ull acc2[8][4];
    #pragma unroll
    for (int i = 0; i < 8; i++)
        #pragma unroll
        for (int j = 0; j < 4; j++) acc2[i][j] = 0ULL;

    const int NK = (Dsz + 7) / 8;   // 38

    {
        float4 av = *(const float4*)aP;
        float4 bv = *(const float4*)bP;
        As[0][half*4+0][arow] = av.x; As[0][half*4+1][arow] = av.y;
        As[0][half*4+2][arow] = av.z; As[0][half*4+3][arow] = av.w;
        Bs[0][half*4+0][arow] = bv.x; Bs[0][half*4+1][arow] = bv.y;
        Bs[0][half*4+2][arow] = bv.z; Bs[0][half*4+3][arow] = bv.w;
    }
    __syncthreads();

    for (int it = 0; it < NK; it++) {
        const int buf = it & 1;
        float4 anx = make_float4(0.f, 0.f, 0.f, 0.f);
        float4 bnx = make_float4(0.f, 0.f, 0.f, 0.f);
        const bool has = (it + 1 < NK);
        if (has) {
            const int k0n = (it + 1) * 8;
            if (k0n + half * 4 < Dsz) {
                anx = *(const float4*)(aP + k0n);
                bnx = *(const float4*)(bP + k0n);
            }
        }

        #pragma unroll
        for (int kk = 0; kk < 8; kk++) {
            float4 a0 = *(const float4*)&As[buf][kk][ty*8];
            float4 a1 = *(const float4*)&As[buf][kk][ty*8+4];
            const double2* bd = (const double2*)&Bs[buf][kk][0];
            double2 b01 = bd[tx*2];
            double2 b23 = bd[tx*2+1];
            ull bb2[4] = { __double_as_longlong(b01.x), __double_as_longlong(b01.y),
                           __double_as_longlong(b23.x), __double_as_longlong(b23.y) };
            float a[8] = {a0.x, a0.y, a0.z, a0.w, a1.x, a1.y, a1.z, a1.w};
            #pragma unroll
            for (int i = 0; i < 8; i++) {
                ull ad; PACK2(ad, a[i]);
                #pragma unroll
                for (int j = 0; j < 4; j++)
                    FMA2(acc2[i][j], ad, bb2[j]);
            }
        }

        if (has) {
            __syncthreads();
            const int nb = buf ^ 1;
            As[nb][half*4+0][arow] = anx.x; As[nb][half*4+1][arow] = anx.y;
            As[nb][half*4+2][arow] = anx.z; As[nb][half*4+3][arow] = anx.w;
            Bs[nb][half*4+0][arow] = bnx.x; Bs[nb][half*4+1][arow] = bnx.y;
            Bs[nb][half*4+2][arow] = bnx.z; Bs[nb][half*4+3][arow] = bnx.w;
            __syncthreads();
        }
    }

    const float4 bv0 = *(const float4*)(bias + g0 + tx*8);
    const float4 bv1 = *(const float4*)(bias + g0 + tx*8 + 4);
    const float bb8[8] = {bv0.x, bv0.y, bv0.z, bv0.w, bv1.x, bv1.y, bv1.z, bv1.w};
    #pragma unroll
    for (int i = 0; i < 8; i++) {
        const size_t sb = (size_t)chunk * 128 + ty*8 + i;
        float* outp = g_GI + (((size_t)dir * Ssz + t) * Bsz + sb) * Gsz + g0 + tx*8;
        float o[8];
        #pragma unroll
        for (int j = 0; j < 4; j++) {
            o[2*j]   = f2lo(acc2[i][j]) + bb8[2*j];
            o[2*j+1] = f2hi(acc2[i][j]) + bb8[2*j+1];
        }
        *(float4*)outp       = make_float4(o[0], o[1], o[2], o[3]);
        *(float4*)(outp + 4) = make_float4(o[4], o[5], o[6], o[7]);
    }
}

// ---------------------------------------------------------------------------
// Kernel 2: GRU recurrence, f32x2 over row pairs, TMA-pipelined weights.
// Task r (sorted by steps desc) -> bid mapping pairs long+short tasks on
// the same SM (bid and bid+148 share LUT_classic[bid%148]).
// Weights stream g_W4 slab-by-slab (24 KB/k4) into a 3-stage smem ring via
// cp.async.bulk; mainloop reads weights via LDS only. t=0 mainloop skipped
// (h0 = 0 => recurrent term is zero).
// ---------------------------------------------------------------------------
__global__ __launch_bounds__(256, 2) void k_gru(
    const float* __restrict__ bhh_f, const float* __restrict__ bhh_b,
    const int* __restrict__ lens)
{
    extern __shared__ __align__(128) unsigned char dsm[];
    float* hA = (float*)(dsm + OFF_HA);
    float* hB = (float*)(dsm + OFF_HB);
    int*  slen = (int*)(dsm + OFF_SLEN);
    int*  srow = (int*)(dsm + OFF_SROW);
    const uint32_t mb0 = smem_u32(dsm + OFF_MB);
    const uint32_t wst = smem_u32(dsm + OFF_W);

    const int tid = threadIdx.x;
    const int bid = blockIdx.x;
    const int r   = (bid < 148) ? bid : (403 - bid);   // steps-desc task rank
    const int dir = r & 1;
    const int grp = 127 - (r >> 1);

    const float* __restrict__ bhh = dir ? bhh_b : bhh_f;
    const float* __restrict__ wsrc0 = g_W4 + (size_t)dir * (Hsz/4) * Gsz * 4;

    if (tid < Rr) {
        const int b = g_order[grp * Rr + tid];
        srow[tid] = b;
        slen[tid] = lens[b];
    }
    if (tid == 0) {
        #pragma unroll
        for (int ss = 0; ss < NST; ss++) mbar_init(mb0 + ss * 8, 1);
    }
    for (int i = tid; i < Rr * Hsz; i += 256) hA[i] = 0.f;
    __syncthreads();

    int maxT = 0;
    #pragma unroll
    for (int q = 0; q < Rr; q++) maxT = max(maxT, slen[q]);

    const int total = (maxT - 1) * 128;   // k4-slabs consumed (t=0 skipped)

    // prologue: fill pipeline
    if (tid == 0) {
        const int nf = total < NST ? total : NST;
        for (int i = 0; i < nf; i++) {
            mbar_expect_tx(mb0 + i * 8, WBYTES);
            bulk_g2s(wst + i * WBYTES, wsrc0 + (size_t)i * (Gsz * 4), WBYTES, mb0 + i * 8);
        }
    }

    const int j0 = tid;
    const int j1 = tid + 256;

    const float bR0 = bhh[j0], bZ0 = bhh[j0 + Hsz], bN0 = bhh[j0 + 2*Hsz];
    const float bR1 = bhh[j1], bZ1 = bhh[j1 + Hsz], bN1 = bhh[j1 + 2*Hsz];

    float sum0[Rr], sum1[Rr];
    #pragma unroll
    for (int q = 0; q < Rr; q++) { sum0[q] = 0.f; sum1[q] = 0.f; }

    float* hcur = hA;
    float* hnxt = hB;
    int c = 0;   // consume index into the weight stream

    for (int t = 0; t < maxT; t++) {
        ull aR0[4], aZ0[4], aN0[4], aR1[4], aZ1[4], aN1[4];
        #pragma unroll
        for (int p = 0; p < 4; p++) {
            aR0[p] = 0ULL; aZ0[p] = 0ULL; aN0[p] = 0ULL;
            aR1[p] = 0ULL; aZ1[p] = 0ULL; aN1[p] = 0ULL;
        }

        if (t > 0) {
            const double2* hb = (const double2*)hcur;   // [pair*256 + k/2]
            #pragma unroll 1
            for (int k4 = 0; k4 < Hsz / 4; k4++) {
                const int st = c % NST;
                mbar_wait(mb0 + st * 8, (c / NST) & 1);

                const float4* ws = (const float4*)(dsm + OFF_W + st * WBYTES);
                const float4 vr0 = ws[j0];
                const float4 vz0 = ws[j0 + Hsz];
                const float4 vn0 = ws[j0 + 2*Hsz];
                const float4 vr1 = ws[j1];
                const float4 vz1 = ws[j1 + Hsz];
                const float4 vn1 = ws[j1 + 2*Hsz];

                ull h0[4], h1[4], h2[4], h3[4];
                #pragma unroll
                for (int p = 0; p < 4; p++) {
                    double2 dA = hb[p * 256 + 2*k4];
                    double2 dB = hb[p * 256 + 2*k4 + 1];
                    h0[p] = __double_as_longlong(dA.x);
                    h1[p] = __double_as_longlong(dA.y);
                    h2[p] = __double_as_longlong(dB.x);
                    h3[p] = __double_as_longlong(dB.y);
                }

#define DOKK(C, HARR) do {                                                     \
    ull w0r, w0z, w0n, w1r, w1z, w1n;                                          \
    PACK2(w0r, vr0.C); PACK2(w0z, vz0.C); PACK2(w0n, vn0.C);                   \
    PACK2(w1r, vr1.C); PACK2(w1z, vz1.C); PACK2(w1n, vn1.C);                   \
    _Pragma("unroll")                                                          \
    for (int p = 0; p < 4; p++) {                                              \
        FMA2(aR0[p], w0r, HARR[p]); FMA2(aZ0[p], w0z, HARR[p]);                \
        FMA2(aN0[p], w0n, HARR[p]);                                            \
        FMA2(aR1[p], w1r, HARR[p]); FMA2(aZ1[p], w1z, HARR[p]);                \
        FMA2(aN1[p], w1n, HARR[p]);                                            \
    } } while (0)

                DOKK(x, h0);
                DOKK(y, h1);
                DOKK(z, h2);
                DOKK(w, h3);
#undef DOKK

                // everyone done reading stage st for this fill -> safe to refill
                __syncthreads();
                if (tid == 0 && c + NST < total) {
                    const int nk4 = (c + NST) & 127;
                    mbar_expect_tx(mb0 + st * 8, WBYTES);
                    bulk_g2s(wst + st * WBYTES, wsrc0 + (size_t)nk4 * (Gsz * 4),
                             WBYTES, mb0 + st * 8);
                }
                c++;
            }
        }

        // epilogue: gates + h update + masked accumulation
        #pragma unroll
        for (int q = 0; q < Rr; q++) {
            const int p = q >> 1;
            const int cc = q & 1;
            const float* __restrict__ gi =
                g_GI + (((size_t)dir * Ssz + t) * Bsz + grp * Rr + q) * Gsz;
            const float m = (t < slen[q]) ? 1.f : 0.f;
            {
                const float aR = cc ? f2hi(aR0[p]) : f2lo(aR0[p]);
                const float aZ = cc ? f2hi(aZ0[p]) : f2lo(aZ0[p]);
                const float aN = cc ? f2hi(aN0[p]) : f2lo(aN0[p]);
                float rg = sigm(gi[j0]          + aR + bR0);
                float zg = sigm(gi[j0 + Hsz]    + aZ + bZ0);
                float ng = tanhf(gi[j0 + 2*Hsz] + rg * (aN + bN0));
                float hv = hcur[(p * Hsz + j0) * 2 + cc];
                float hn = ng + zg * (hv - ng);    // (1-z)*n + z*h
                hnxt[(p * Hsz + j0) * 2 + cc] = hn;
                sum0[q] += hn * m;
            }
            {
                const float aR = cc ? f2hi(aR1[p]) : f2lo(aR1[p]);
                const float aZ = cc ? f2hi(aZ1[p]) : f2lo(aZ1[p]);
                const float aN = cc ? f2hi(aN1[p]) : f2lo(aN1[p]);
                float rg = sigm(gi[j1]          + aR + bR1);
                float zg = sigm(gi[j1 + Hsz]    + aZ + bZ1);
                float ng = tanhf(gi[j1 + 2*Hsz] + rg * (aN + bN1));
                float hv = hcur[(p * Hsz + j1) * 2 + cc];
                float hn = ng + zg * (hv - ng);
                hnxt[(p * Hsz + j1) * 2 + cc] = hn;
                sum1[q] += hn * m;
            }
        }
        __syncthreads();
        float* tp = hcur; hcur = hnxt; hnxt = tp;
    }

    #pragma unroll
    for (int q = 0; q < Rr; q++) {
        g_part[((size_t)dir * Bsz + srow[q]) * Hsz + j0] = sum0[q];
        g_part[((size_t)dir * Bsz + srow[q]) * Hsz + j1] = sum1[q];
    }
}

// ---------------------------------------------------------------------------
// Kernel 3: avg = 0.5*(sum_f + sum_b)/len; mu/sigma heads; reparam sample.
// Output layout: [final (B*Z) | mu (B*Z) | sigma (B*Z)]
// ---------------------------------------------------------------------------
__global__ __launch_bounds__(128) void k_head(
    const float* __restrict__ Wmu, const float* __restrict__ bmu,
    const float* __restrict__ Wsg, const float* __restrict__ bsg,
    const float* __restrict__ eps, const int* __restrict__ lens,
    float* __restrict__ out)
{
    __shared__ float avg[Hsz];
    const int b = blockIdx.x;
    const int tid = threadIdx.x;
    const float inv = 0.5f / (float)lens[b];   // mask.sum(0) == len
    for (int i = tid; i < Hsz; i += 128)
        avg[i] = (g_part[(size_t)b * Hsz + i] +
                  g_part[((size_t)Bsz + b) * Hsz + i]) * inv;
    __syncthreads();

    const float4* a4 = (const float4*)avg;
    const float4* wm = (const float4*)(Wmu + (size_t)tid * Hsz);
    const float4* ws = (const float4*)(Wsg + (size_t)tid * Hsz);
    float sm = 0.f, ss = 0.f;
    #pragma unroll 4
    for (int i = 0; i < Hsz / 4; i++) {
        float4 a = a4[i];
        sm = dot4(wm[i], a, sm);
        ss = dot4(ws[i], a, ss);
    }
    sm += bmu[tid];
    ss += bsg[tid];
    float mu = (sm >= 0.f) ? sm : 0.2f * sm;   // leaky relu 0.2
    float ls = (ss >= 0.f) ? ss : 0.2f * ss;
    float sg = expf(ls);
    float fin = fmaf(eps[(size_t)b * Zsz + tid], sg, mu);
    out[(size_t)b * Zsz + tid]              = fin;
    out[((size_t)Bsz + b) * Zsz + tid]      = mu;
    out[((size_t)2 * Bsz + b) * Zsz + tid]  = sg;
}

extern "C" void kernel_launch(void* const* d_in, const int* in_sizes, int n_in,
                              void* d_out, int out_size)
{
    const float* text  = (const float*)d_in[0];
    const int*   lens  = (const int*)  d_in[1];
    const float* Wih_f = (const float*)d_in[2];
    const float* Whh_f = (const float*)d_in[3];
    const float* bih_f = (const float*)d_in[4];
    const float* bhh_f = (const float*)d_in[5];
    const float* Wih_b = (const float*)d_in[6];
    const float* Whh_b = (const float*)d_in[7];
    const float* bih_b = (const float*)d_in[8];
    const float* bhh_b = (const float*)d_in[9];
    const float* W_mu  = (const float*)d_in[10];
    const float* b_mu  = (const float*)d_in[11];
    const float* W_sig = (const float*)d_in[12];
    const float* b_sig = (const float*)d_in[13];
    const float* eps   = (const float*)d_in[14];
    float* out = (float*)d_out;

    cudaFuncSetAttribute(k_gru, cudaFuncAttributeMaxDynamicSharedMemorySize, SMEM_GRU);

    // 0) length sort + packed weight layout (one-time, cheap)
    k_sort<<<1, Bsz>>>(lens);
    {
        const size_t total = (size_t)2 * (Hsz/4) * Gsz * 4;
        k_wt4<<<(unsigned)((total + 255) / 256), 256>>>(Whh_f, Whh_b);
    }
    // 1) GI (t-major over sorted rows; dead tiles skipped)
    k_gi_gemm<<<dim3(8 * Ssz, (2 * Gsz) / 128), 256>>>(
        text, Wih_f, bih_f, Wih_b, bih_b, lens);
    // 2) GRU scan (balanced long+short pairing, TMA weight pipeline)
    k_gru<<<256, 256, SMEM_GRU>>>(bhh_f, bhh_b, lens);
    // 3) Average + VAE heads + reparameterized sample
    k_head<<<Bsz, 128>>>(W_mu, b_mu, W_sig, b_sig, eps, lens, out);
}

// round 10
// speedup vs baseline: 5.1167x; 1.1022x over previous
#include <cuda_runtime.h>
#include <math.h>
#include <stddef.h>
#include <stdint.h>

namespace {
constexpr int Bsz = 1024;
constexpr int Ssz = 64;
constexpr int Dsz = 300;
constexpr int Hsz = 512;
constexpr int Gsz = 1536;   // 3H
constexpr int Zsz = 128;
constexpr int MR  = Bsz * Ssz;   // 65536
constexpr int Rr  = 8;           // batch rows per GRU CTA (4 f32x2 pairs)

constexpr int NST    = 3;                       // weight pipeline stages
constexpr int WBYTES = Gsz * 4 * 4;             // 24576 B per k4 slab
constexpr int OFF_W    = 0;
constexpr int OFF_HA   = NST * WBYTES;          // 73728
constexpr int OFF_HB   = OFF_HA + Rr * Hsz * 4; // +16384
constexpr int OFF_MBF  = OFF_HB + Rr * Hsz * 4; // full barriers (3 x 8B)
constexpr int OFF_MBE  = OFF_MBF + NST * 8;     // empty barriers (3 x 8B)
constexpr int OFF_SLEN = OFF_MBE + NST * 8;
constexpr int OFF_SROW = OFF_SLEN + Rr * 4;
constexpr int SMEM_GRU = OFF_SROW + Rr * 4 + 64;   // ~106.7 KB -> 2 CTAs/SM
}

typedef unsigned long long ull;

// Scratch (allocation-free rule: __device__ globals)
__device__ float g_GI[(size_t)2 * MR * Gsz];          // [dir][t][sorted_b][3H]
__device__ float g_part[(size_t)2 * Bsz * Hsz];       // masked hidden sums per direction
__device__ float g_W4[(size_t)2 * (Hsz/4) * Gsz * 4]; // packed Whh: [dir][k/4][g][kk]
__device__ int   g_order[Bsz];                        // rows sorted by length (ascending)

// packed f32x2 helpers (FFMA2 — 2 exact fp32 FMAs per instruction)
#define FMA2(acc, a, b) \
    asm("fma.rn.f32x2 %0, %1, %2, %0;" : "+l"(acc) : "l"(a), "l"(b))
#define PACK2(d, s) \
    asm("mov.b64 %0, {%1, %1};" : "=l"(d) : "f"(s))

__device__ __forceinline__ float f2lo(ull u) { return __uint_as_float((unsigned)u); }
__device__ __forceinline__ float f2hi(ull u) { return __uint_as_float((unsigned)(u >> 32)); }

__device__ __forceinline__ uint32_t smem_u32(const void* p) {
    return (uint32_t)__cvta_generic_to_shared(p);
}

__device__ __forceinline__ void mbar_init(uint32_t mbar, uint32_t cnt) {
    asm volatile("mbarrier.init.shared.b64 [%0], %1;" :: "r"(mbar), "r"(cnt) : "memory");
}
__device__ __forceinline__ void mbar_expect_tx(uint32_t mbar, uint32_t bytes) {
    asm volatile("mbarrier.arrive.expect_tx.shared.b64 _, [%0], %1;"
                 :: "r"(mbar), "r"(bytes) : "memory");
}
__device__ __forceinline__ void mbar_arrive(uint32_t mbar) {
    asm volatile("mbarrier.arrive.shared.b64 _, [%0];" :: "r"(mbar) : "memory");
}
__device__ __forceinline__ void mbar_wait(uint32_t mbar, uint32_t phase) {
    uint32_t done;
    asm volatile("{\n\t.reg .pred p;\n\t"
        "mbarrier.try_wait.parity.acquire.cta.shared::cta.b64 p, [%1], %2;\n\t"
        "selp.b32 %0, 1, 0, p;\n\t}"
        : "=r"(done) : "r"(mbar), "r"(phase) : "memory");
    while (!done) {
        asm volatile("{\n\t.reg .pred p;\n\t"
            "mbarrier.try_wait.parity.acquire.cta.shared::cta.b64 p, [%1], %2, 0x989680;\n\t"
            "selp.b32 %0, 1, 0, p;\n\t}"
            : "=r"(done) : "r"(mbar), "r"(phase) : "memory");
    }
}
__device__ __forceinline__ void bulk_g2s(uint32_t dst, const void* src,
                                         uint32_t bytes, uint32_t mbar) {
    asm volatile(
        "cp.async.bulk.shared::cluster.global.mbarrier::complete_tx::bytes "
        "[%0], [%1], %2, [%3];"
        :: "r"(dst), "l"(src), "r"(bytes), "r"(mbar) : "memory");
}

__device__ __forceinline__ float dot4(float4 w, float4 h, float a) {
    a = fmaf(w.x, h.x, a);
    a = fmaf(w.y, h.y, a);
    a = fmaf(w.z, h.z, a);
    a = fmaf(w.w, h.w, a);
    return a;
}

__device__ __forceinline__ float sigm(float x) {
    return 1.f / (1.f + __expf(-x));
}

// ---------------------------------------------------------------------------
// Sort rows by length (counting sort, single block). Output values are
// permutation-invariant within equal-length bins.
// ---------------------------------------------------------------------------
__global__ void k_sort(const int* __restrict__ lens)
{
    __shared__ int hist[Ssz + 1];
    __shared__ int off[Ssz + 2];
    const int tid = threadIdx.x;
    if (tid <= Ssz) hist[tid] = 0;
    __syncthreads();
    const int l = lens[tid];
    atomicAdd(&hist[l], 1);
    __syncthreads();
    if (tid == 0) {
        int run = 0;
        for (int i = 1; i <= Ssz; i++) { off[i] = run; run += hist[i]; }
    }
    __syncthreads();
    int pos = atomicAdd(&off[l], 1);
    g_order[pos] = tid;
}

// ---------------------------------------------------------------------------
// Repack Whh -> W4[dir][k/4][g][kk]
// ---------------------------------------------------------------------------
__global__ __launch_bounds__(256) void k_wt4(
    const float* __restrict__ Whh_f, const float* __restrict__ Whh_b)
{
    size_t idx = (size_t)blockIdx.x * 256 + threadIdx.x;
    const size_t per = (size_t)(Hsz/4) * Gsz * 4;
    if (idx >= 2 * per) return;
    const int dir = (int)(idx / per);
    size_t rem = idx - (size_t)dir * per;
    const int kk = (int)(rem & 3);
    size_t r2 = rem >> 2;
    const int g  = (int)(r2 % Gsz);
    const int k4 = (int)(r2 / Gsz);
    const float* W = dir ? Whh_b : Whh_f;
    g_W4[idx] = W[(size_t)g * Hsz + k4 * 4 + kk];
}

// ---------------------------------------------------------------------------
// Kernel 1: GI[dir][t][sorted_b][g] = x[order(sb)][dir? 63-t : t] @ Wih.T + b.
// t-major layout over length-sorted rows; tiles with t >= chunk-max-length
// exit immediately. 128x128x8 tiles, 256 threads, 8x8 microtile (f32x2).
// ---------------------------------------------------------------------------
__global__ __launch_bounds__(256) void k_gi_gemm(
    const float* __restrict__ X,
    const float* __restrict__ Wf, const float* __restrict__ bf,
    const float* __restrict__ Wb, const float* __restrict__ bb,
    const int* __restrict__ lens)
{
    __shared__ __align__(16) float As[2][8][128];
    __shared__ __align__(16) float Bs[2][8][128];

    const int bx = blockIdx.x;
    const int chunk = bx >> 6;
    const int t = bx & 63;

    if (t >= lens[g_order[chunk * 128 + 127]]) return;

    const int tid = threadIdx.x;
    const int n0 = blockIdx.y * 128;
    const int dir = (n0 >= Gsz) ? 1 : 0;
    const float* __restrict__ W    = dir ? Wb : Wf;
    const float* __restrict__ bias = dir ? bb : bf;
    const int g0 = n0 - dir * Gsz;
    const int s  = dir ? (Ssz - 1 - t) : t;     // backward pre-reads reversed x

    const int tx = tid & 15;
    const int ty = tid >> 4;

    const int arow = tid >> 1;       // 0..127
    const int half = tid & 1;        // 0/1 -> k offset 0/4

    const int browB = g_order[chunk * 128 + arow];
    const float* aP = X + ((size_t)browB * Ssz + s) * Dsz + half * 4;
    const float* bP = W + (size_t)(g0 + arow) * Dsz + half * 4;

    ull acc2[8][4];
    #pragma unroll
    for (int i = 0; i < 8; i++)
        #pragma unroll
        for (int j = 0; j < 4; j++) acc2[i][j] = 0ULL;

    const int NK = (Dsz + 7) / 8;   // 38

    {
        float4 av = *(const float4*)aP;
        float4 bv = *(const float4*)bP;
        As[0][half*4+0][arow] = av.x; As[0][half*4+1][arow] = av.y;
        As[0][half*4+2][arow] = av.z; As[0][half*4+3][arow] = av.w;
        Bs[0][half*4+0][arow] = bv.x; Bs[0][half*4+1][arow] = bv.y;
        Bs[0][half*4+2][arow] = bv.z; Bs[0][half*4+3][arow] = bv.w;
    }
    __syncthreads();

    for (int it = 0; it < NK; it++) {
        const int buf = it & 1;
        float4 anx = make_float4(0.f, 0.f, 0.f, 0.f);
        float4 bnx = make_float4(0.f, 0.f, 0.f, 0.f);
        const bool has = (it + 1 < NK);
        if (has) {
            const int k0n = (it + 1) * 8;
            if (k0n + half * 4 < Dsz) {
                anx = *(const float4*)(aP + k0n);
                bnx = *(const float4*)(bP + k0n);
            }
        }

        #pragma unroll
        for (int kk = 0; kk < 8; kk++) {
            float4 a0 = *(const float4*)&As[buf][kk][ty*8];
            float4 a1 = *(const float4*)&As[buf][kk][ty*8+4];
            const double2* bd = (const double2*)&Bs[buf][kk][0];
            double2 b01 = bd[tx*2];
            double2 b23 = bd[tx*2+1];
            ull bb2[4] = { __double_as_longlong(b01.x), __double_as_longlong(b01.y),
                           __double_as_longlong(b23.x), __double_as_longlong(b23.y) };
            float a[8] = {a0.x, a0.y, a0.z, a0.w, a1.x, a1.y, a1.z, a1.w};
            #pragma unroll
            for (int i = 0; i < 8; i++) {
                ull ad; PACK2(ad, a[i]);
                #pragma unroll
                for (int j = 0; j < 4; j++)
                    FMA2(acc2[i][j], ad, bb2[j]);
            }
        }

        if (has) {
            __syncthreads();
            const int nb = buf ^ 1;
            As[nb][half*4+0][arow] = anx.x; As[nb][half*4+1][arow] = anx.y;
            As[nb][half*4+2][arow] = anx.z; As[nb][half*4+3][arow] = anx.w;
            Bs[nb][half*4+0][arow] = bnx.x; Bs[nb][half*4+1][arow] = bnx.y;
            Bs[nb][half*4+2][arow] = bnx.z; Bs[nb][half*4+3][arow] = bnx.w;
            __syncthreads();
        }
    }

    const float4 bv0 = *(const float4*)(bias + g0 + tx*8);
    const float4 bv1 = *(const float4*)(bias + g0 + tx*8 + 4);
    const float bb8[8] = {bv0.x, bv0.y, bv0.z, bv0.w, bv1.x, bv1.y, bv1.z, bv1.w};
    #pragma unroll
    for (int i = 0; i < 8; i++) {
        const size_t sb = (size_t)chunk * 128 + ty*8 + i;
        float* outp = g_GI + (((size_t)dir * Ssz + t) * Bsz + sb) * Gsz + g0 + tx*8;
        float o[8];
        #pragma unroll
        for (int j = 0; j < 4; j++) {
            o[2*j]   = f2lo(acc2[i][j]) + bb8[2*j];
            o[2*j+1] = f2hi(acc2[i][j]) + bb8[2*j+1];
        }
        *(float4*)outp       = make_float4(o[0], o[1], o[2], o[3]);
        *(float4*)(outp + 4) = make_float4(o[4], o[5], o[6], o[7]);
    }
}

// ---------------------------------------------------------------------------
// Kernel 2: GRU recurrence, f32x2, TMA weight ring with full/empty mbarriers.
// NO CTA-wide sync inside the k-loop: consumers (8 warps) wait full[st],
// load, arrive empty[st]; producer (tid 0) waits empty[st] (8 arrives) and
// re-issues cp.async.bulk for slab c+NST. Warps may skew up to NST stages,
// hiding TRYWAIT/LDS latency. One __syncthreads per step (h double buffer).
// ---------------------------------------------------------------------------
__global__ __launch_bounds__(256, 2) void k_gru(
    const float* __restrict__ bhh_f, const float* __restrict__ bhh_b,
    const int* __restrict__ lens)
{
    extern __shared__ __align__(128) unsigned char dsm[];
    float* hA = (float*)(dsm + OFF_HA);
    float* hB = (float*)(dsm + OFF_HB);
    int*  slen = (int*)(dsm + OFF_SLEN);
    int*  srow = (int*)(dsm + OFF_SROW);
    const uint32_t mbF = smem_u32(dsm + OFF_MBF);
    const uint32_t mbE = smem_u32(dsm + OFF_MBE);
    const uint32_t wst = smem_u32(dsm + OFF_W);

    const int tid = threadIdx.x;
    const int lane0 = ((tid & 31) == 0);
    const int bid = blockIdx.x;
    const int r   = (bid < 148) ? bid : (403 - bid);   // steps-desc task rank
    const int dir = r & 1;
    const int grp = 127 - (r >> 1);

    const float* __restrict__ bhh = dir ? bhh_b : bhh_f;
    const float* __restrict__ wsrc0 = g_W4 + (size_t)dir * (Hsz/4) * Gsz * 4;

    if (tid < Rr) {
        const int b = g_order[grp * Rr + tid];
        srow[tid] = b;
        slen[tid] = lens[b];
    }
    if (tid == 0) {
        #pragma unroll
        for (int ss = 0; ss < NST; ss++) {
            mbar_init(mbF + ss * 8, 1);   // TMA tx completion
            mbar_init(mbE + ss * 8, 8);   // one arrive per warp
        }
    }
    for (int i = tid; i < Rr * Hsz; i += 256) hA[i] = 0.f;
    __syncthreads();

    int maxT = 0;
    #pragma unroll
    for (int q = 0; q < Rr; q++) maxT = max(maxT, slen[q]);

    const int total = (maxT - 1) * 128;   // k4-slabs consumed (t=0 skipped)

    // prologue: fill pipeline
    if (tid == 0) {
        const int nf = total < NST ? total : NST;
        for (int i = 0; i < nf; i++) {
            mbar_expect_tx(mbF + i * 8, WBYTES);
            bulk_g2s(wst + i * WBYTES, wsrc0 + (size_t)i * (Gsz * 4), WBYTES, mbF + i * 8);
        }
    }

    const int j0 = tid;
    const int j1 = tid + 256;

    const float bR0 = bhh[j0], bZ0 = bhh[j0 + Hsz], bN0 = bhh[j0 + 2*Hsz];
    const float bR1 = bhh[j1], bZ1 = bhh[j1 + Hsz], bN1 = bhh[j1 + 2*Hsz];

    float sum0[Rr], sum1[Rr];
    #pragma unroll
    for (int q = 0; q < Rr; q++) { sum0[q] = 0.f; sum1[q] = 0.f; }

    float* hcur = hA;
    float* hnxt = hB;
    int c = 0;     // global slab consumption counter
    int st = 0;    // stage = c % NST
    int ph = 0;    // phase = (c / NST) & 1

    for (int t = 0; t < maxT; t++) {
        ull aR0[4], aZ0[4], aN0[4], aR1[4], aZ1[4], aN1[4];
        #pragma unroll
        for (int p = 0; p < 4; p++) {
            aR0[p] = 0ULL; aZ0[p] = 0ULL; aN0[p] = 0ULL;
            aR1[p] = 0ULL; aZ1[p] = 0ULL; aN1[p] = 0ULL;
        }

        if (t > 0) {
            const double2* hb = (const double2*)hcur;   // [pair*256 + k/2]
            #pragma unroll 1
            for (int k4 = 0; k4 < Hsz / 4; k4++) {
                mbar_wait(mbF + st * 8, ph);

                const float4* ws = (const float4*)(dsm + OFF_W + st * WBYTES);
                const float4 vr0 = ws[j0];
                const float4 vz0 = ws[j0 + Hsz];
                const float4 vn0 = ws[j0 + 2*Hsz];
                const float4 vr1 = ws[j1];
                const float4 vz1 = ws[j1 + Hsz];
                const float4 vn1 = ws[j1 + 2*Hsz];

                // weights for this stage are in registers -> release the stage
                if (lane0) mbar_arrive(mbE + st * 8);

                ull h0[4], h1[4], h2[4], h3[4];
                #pragma unroll
                for (int p = 0; p < 4; p++) {
                    double2 dA = hb[p * 256 + 2*k4];
                    double2 dB = hb[p * 256 + 2*k4 + 1];
                    h0[p] = __double_as_longlong(dA.x);
                    h1[p] = __double_as_longlong(dA.y);
                    h2[p] = __double_as_longlong(dB.x);
                    h3[p] = __double_as_longlong(dB.y);
                }

#define DOKK(C, HARR) do {                                                     \
    ull w0r, w0z, w0n, w1r, w1z, w1n;                                          \
    PACK2(w0r, vr0.C); PACK2(w0z, vz0.C); PACK2(w0n, vn0.C);                   \
    PACK2(w1r, vr1.C); PACK2(w1z, vz1.C); PACK2(w1n, vn1.C);                   \
    _Pragma("unroll")                                                          \
    for (int p = 0; p < 4; p++) {                                              \
        FMA2(aR0[p], w0r, HARR[p]); FMA2(aZ0[p], w0z, HARR[p]);                \
        FMA2(aN0[p], w0n, HARR[p]);                                            \
        FMA2(aR1[p], w1r, HARR[p]); FMA2(aZ1[p], w1z, HARR[p]);                \
        FMA2(aN1[p], w1n, HARR[p]);                                            \
    } } while (0)

                DOKK(x, h0);
                DOKK(y, h1);
                DOKK(z, h2);
                DOKK(w, h3);
#undef DOKK

                // producer: refill this stage with slab c+NST once all warps
                // have released it (8 arrives on empty[st], round parity ph)
                if (tid == 0 && c + NST < total) {
                    mbar_wait(mbE + st * 8, ph);
                    mbar_expect_tx(mbF + st * 8, WBYTES);
                    bulk_g2s(wst + st * WBYTES,
                             wsrc0 + (size_t)((c + NST) & 127) * (Gsz * 4),
                             WBYTES, mbF + st * 8);
                }
                c++;
                if (++st == NST) { st = 0; ph ^= 1; }
            }
        }

        // epilogue: gates + h update + masked accumulation
        const int tsrc_unused = 0; (void)tsrc_unused;
        #pragma unroll
        for (int q = 0; q < Rr; q++) {
            const int p = q >> 1;
            const int cc = q & 1;
            const float* __restrict__ gi =
                g_GI + (((size_t)dir * Ssz + t) * Bsz + grp * Rr + q) * Gsz;
            const float m = (t < slen[q]) ? 1.f : 0.f;
            {
                const float aR = cc ? f2hi(aR0[p]) : f2lo(aR0[p]);
                const float aZ = cc ? f2hi(aZ0[p]) : f2lo(aZ0[p]);
                const float aN = cc ? f2hi(aN0[p]) : f2lo(aN0[p]);
                float rg = sigm(gi[j0]          + aR + bR0);
                float zg = sigm(gi[j0 + Hsz]    + aZ + bZ0);
                float ng = tanhf(gi[j0 + 2*Hsz] + rg * (aN + bN0));
                float hv = hcur[(p * Hsz + j0) * 2 + cc];
                float hn = ng + zg * (hv - ng);    // (1-z)*n + z*h
                hnxt[(p * Hsz + j0) * 2 + cc] = hn;
                sum0[q] += hn * m;
            }
            {
                const float aR = cc ? f2hi(aR1[p]) : f2lo(aR1[p]);
                const float aZ = cc ? f2hi(aZ1[p]) : f2lo(aZ1[p]);
                const float aN = cc ? f2hi(aN1[p]) : f2lo(aN1[p]);
                float rg = sigm(gi[j1]          + aR + bR1);
                float zg = sigm(gi[j1 + Hsz]    + aZ + bZ1);
                float ng = tanhf(gi[j1 + 2*Hsz] + rg * (aN + bN1));
                float hv = hcur[(p * Hsz + j1) * 2 + cc];
                float hn = ng + zg * (hv - ng);
                hnxt[(p * Hsz + j1) * 2 + cc] = hn;
                sum1[q] += hn * m;
            }
        }
        __syncthreads();
        float* tp = hcur; hcur = hnxt; hnxt = tp;
    }

    #pragma unroll
    for (int q = 0; q < Rr; q++) {
        g_part[((size_t)dir * Bsz + srow[q]) * Hsz + j0] = sum0[q];
        g_part[((size_t)dir * Bsz + srow[q]) * Hsz + j1] = sum1[q];
    }
}

// ---------------------------------------------------------------------------
// Kernel 3: avg = 0.5*(sum_f + sum_b)/len; mu/sigma heads; reparam sample.
// Output layout: [final (B*Z) | mu (B*Z) | sigma (B*Z)]
// ---------------------------------------------------------------------------
__global__ __launch_bounds__(128) void k_head(
    const float* __restrict__ Wmu, const float* __restrict__ bmu,
    const float* __restrict__ Wsg, const float* __restrict__ bsg,
    const float* __restrict__ eps, const int* __restrict__ lens,
    float* __restrict__ out)
{
    __shared__ float avg[Hsz];
    const int b = blockIdx.x;
    const int tid = threadIdx.x;
    const float inv = 0.5f / (float)lens[b];   // mask.sum(0) == len
    for (int i = tid; i < Hsz; i += 128)
        avg[i] = (g_part[(size_t)b * Hsz + i] +
                  g_part[((size_t)Bsz + b) * Hsz + i]) * inv;
    __syncthreads();

    const float4* a4 = (const float4*)avg;
    const float4* wm = (const float4*)(Wmu + (size_t)tid * Hsz);
    const float4* ws = (const float4*)(Wsg + (size_t)tid * Hsz);
    float sm = 0.f, ss = 0.f;
    #pragma unroll 4
    for (int i = 0; i < Hsz / 4; i++) {
        float4 a = a4[i];
        sm = dot4(wm[i], a, sm);
        ss = dot4(ws[i], a, ss);
    }
    sm += bmu[tid];
    ss += bsg[tid];
    float mu = (sm >= 0.f) ? sm : 0.2f * sm;   // leaky relu 0.2
    float ls = (ss >= 0.f) ? ss : 0.2f * ss;
    float sg = expf(ls);
    float fin = fmaf(eps[(size_t)b * Zsz + tid], sg, mu);
    out[(size_t)b * Zsz + tid]              = fin;
    out[((size_t)Bsz + b) * Zsz + tid]      = mu;
    out[((size_t)2 * Bsz + b) * Zsz + tid]  = sg;
}

extern "C" void kernel_launch(void* const* d_in, const int* in_sizes, int n_in,
                              void* d_out, int out_size)
{
    const float* text  = (const float*)d_in[0];
    const int*   lens  = (const int*)  d_in[1];
    const float* Wih_f = (const float*)d_in[2];
    const float* Whh_f = (const float*)d_in[3];
    const float* bih_f = (const float*)d_in[4];
    const float* bhh_f = (const float*)d_in[5];
    const float* Wih_b = (const float*)d_in[6];
    const float* Whh_b = (const float*)d_in[7];
    const float* bih_b = (const float*)d_in[8];
    const float* bhh_b = (const float*)d_in[9];
    const float* W_mu  = (const float*)d_in[10];
    const float* b_mu  = (const float*)d_in[11];
    const float* W_sig = (const float*)d_in[12];
    const float* b_sig = (const float*)d_in[13];
    const float* eps   = (const float*)d_in[14];
    float* out = (float*)d_out;

    cudaFuncSetAttribute(k_gru, cudaFuncAttributeMaxDynamicSharedMemorySize, SMEM_GRU);

    // 0) length sort + packed weight layout (one-time, cheap)
    k_sort<<<1, Bsz>>>(lens);
    {
        const size_t total = (size_t)2 * (Hsz/4) * Gsz * 4;
        k_wt4<<<(unsigned)((total + 255) / 256), 256>>>(Whh_f, Whh_b);
    }
    // 1) GI (t-major over sorted rows; dead tiles skipped)
    k_gi_gemm<<<dim3(8 * Ssz, (2 * Gsz) / 128), 256>>>(
        text, Wih_f, bih_f, Wih_b, bih_b, lens);
    // 2) GRU scan (balanced pairing, decoupled full/empty TMA ring)
    k_gru<<<256, 256, SMEM_GRU>>>(bhh_f, bhh_b, lens);
    // 3) Average + VAE heads + reparameterized sample
    k_head<<<Bsz, 128>>>(W_mu, b_mu, W_sig, b_sig, eps, lens, out);
}

// round 15
// speedup vs baseline: 5.1365x; 1.0039x over previous
#include <cuda_runtime.h>
#include <math.h>
#include <stddef.h>
#include <stdint.h>

namespace {
constexpr int Bsz = 1024;
constexpr int Ssz = 64;
constexpr int Dsz = 300;
constexpr int Hsz = 512;
constexpr int Gsz = 1536;   // 3H
constexpr int Zsz = 128;
constexpr int MR  = Bsz * Ssz;   // 65536
constexpr int Rr  = 8;           // batch rows per GRU CTA (4 f32x2 pairs)

constexpr int NST    = 3;                       // weight pipeline stages
constexpr int WBYTES = Gsz * 4 * 4;             // 24576 B per k4 slab
constexpr int OFF_W    = 0;
constexpr int OFF_HA   = NST * WBYTES;          // 73728
constexpr int OFF_HB   = OFF_HA + Rr * Hsz * 4; // +16384
constexpr int OFF_MBF  = OFF_HB + Rr * Hsz * 4; // full barriers (3 x 8B)
constexpr int OFF_MBE  = OFF_MBF + NST * 8;     // empty barriers (3 x 8B)
constexpr int OFF_SLEN = OFF_MBE + NST * 8;
constexpr int OFF_SROW = OFF_SLEN + Rr * 4;
constexpr int SMEM_GRU = OFF_SROW + Rr * 4 + 64;   // ~106.7 KB -> 2 CTAs/SM
}

typedef unsigned long long ull;

// Scratch (allocation-free rule: __device__ globals)
__device__ float g_GI[(size_t)2 * MR * Gsz];          // [dir][t][sorted_b][3H]
__device__ float g_part[(size_t)2 * Bsz * Hsz];       // masked hidden sums per direction
__device__ float g_W4[(size_t)2 * (Hsz/4) * Gsz * 4]; // packed Whh: [dir][k/4][g][kk]
__device__ int   g_order[Bsz];                        // rows sorted by length (ascending)

// packed f32x2 helpers (FFMA2 — 2 exact fp32 FMAs per instruction)
#define FMA2(acc, a, b) \
    asm("fma.rn.f32x2 %0, %1, %2, %0;" : "+l"(acc) : "l"(a), "l"(b))
#define PACK2(d, s) \
    asm("mov.b64 %0, {%1, %1};" : "=l"(d) : "f"(s))

// consumer-only step barrier (named barrier 1, 256 threads = warps 0..7)
#define BAR_CONS() asm volatile("bar.sync 1, 256;" ::: "memory")

__device__ __forceinline__ float f2lo(ull u) { return __uint_as_float((unsigned)u); }
__device__ __forceinline__ float f2hi(ull u) { return __uint_as_float((unsigned)(u >> 32)); }

__device__ __forceinline__ uint32_t smem_u32(const void* p) {
    return (uint32_t)__cvta_generic_to_shared(p);
}

__device__ __forceinline__ void mbar_init(uint32_t mbar, uint32_t cnt) {
    asm volatile("mbarrier.init.shared.b64 [%0], %1;" :: "r"(mbar), "r"(cnt) : "memory");
}
__device__ __forceinline__ void mbar_expect_tx(uint32_t mbar, uint32_t bytes) {
    asm volatile("mbarrier.arrive.expect_tx.shared.b64 _, [%0], %1;"
                 :: "r"(mbar), "r"(bytes) : "memory");
}
__device__ __forceinline__ void mbar_arrive(uint32_t mbar) {
    asm volatile("mbarrier.arrive.shared.b64 _, [%0];" :: "r"(mbar) : "memory");
}
__device__ __forceinline__ void mbar_wait(uint32_t mbar, uint32_t phase) {
    uint32_t done;
    asm volatile("{\n\t.reg .pred p;\n\t"
        "mbarrier.try_wait.parity.acquire.cta.shared::cta.b64 p, [%1], %2;\n\t"
        "selp.b32 %0, 1, 0, p;\n\t}"
        : "=r"(done) : "r"(mbar), "r"(phase) : "memory");
    while (!done) {
        asm volatile("{\n\t.reg .pred p;\n\t"
            "mbarrier.try_wait.parity.acquire.cta.shared::cta.b64 p, [%1], %2, 0x989680;\n\t"
            "selp.b32 %0, 1, 0, p;\n\t}"
            : "=r"(done) : "r"(mbar), "r"(phase) : "memory");
    }
}
__device__ __forceinline__ void bulk_g2s(uint32_t dst, const void* src,
                                         uint32_t bytes, uint32_t mbar) {
    asm volatile(
        "cp.async.bulk.shared::cluster.global.mbarrier::complete_tx::bytes "
        "[%0], [%1], %2, [%3];"
        :: "r"(dst), "l"(src), "r"(bytes), "r"(mbar) : "memory");
}

__device__ __forceinline__ float dot4(float4 w, float4 h, float a) {
    a = fmaf(w.x, h.x, a);
    a = fmaf(w.y, h.y, a);
    a = fmaf(w.z, h.z, a);
    a = fmaf(w.w, h.w, a);
    return a;
}

__device__ __forceinline__ float sigm(float x) {
    return 1.f / (1.f + __expf(-x));
}

// ---------------------------------------------------------------------------
// Sort rows by length (counting sort, single block). Output values are
// permutation-invariant within equal-length bins.
// ---------------------------------------------------------------------------
__global__ void k_sort(const int* __restrict__ lens)
{
    __shared__ int hist[Ssz + 1];
    __shared__ int off[Ssz + 2];
    const int tid = threadIdx.x;
    if (tid <= Ssz) hist[tid] = 0;
    __syncthreads();
    const int l = lens[tid];
    atomicAdd(&hist[l], 1);
    __syncthreads();
    if (tid == 0) {
        int run = 0;
        for (int i = 1; i <= Ssz; i++) { off[i] = run; run += hist[i]; }
    }
    __syncthreads();
    int pos = atomicAdd(&off[l], 1);
    g_order[pos] = tid;
}

// ---------------------------------------------------------------------------
// Repack Whh -> W4[dir][k/4][g][kk]
// ---------------------------------------------------------------------------
__global__ __launch_bounds__(256) void k_wt4(
    const float* __restrict__ Whh_f, const float* __restrict__ Whh_b)
{
    size_t idx = (size_t)blockIdx.x * 256 + threadIdx.x;
    const size_t per = (size_t)(Hsz/4) * Gsz * 4;
    if (idx >= 2 * per) return;
    const int dir = (int)(idx / per);
    size_t rem = idx - (size_t)dir * per;
    const int kk = (int)(rem & 3);
    size_t r2 = rem >> 2;
    const int g  = (int)(r2 % Gsz);
    const int k4 = (int)(r2 / Gsz);
    const float* W = dir ? Whh_b : Whh_f;
    g_W4[idx] = W[(size_t)g * Hsz + k4 * 4 + kk];
}

// ---------------------------------------------------------------------------
// Kernel 1: GI[dir][t][sorted_b][g] = x[order(sb)][dir? 63-t : t] @ Wih.T + b.
// t-major layout over length-sorted rows; tiles with t >= chunk-max-length
// exit immediately. 128x128x8 tiles, 256 threads, 8x8 microtile (f32x2).
// ---------------------------------------------------------------------------
__global__ __launch_bounds__(256) void k_gi_gemm(
    const float* __restrict__ X,
    const float* __restrict__ Wf, const float* __restrict__ bf,
    const float* __restrict__ Wb, const float* __restrict__ bb,
    const int* __restrict__ lens)
{
    __shared__ __align__(16) float As[2][8][128];
    __shared__ __align__(16) float Bs[2][8][128];

    const int bx = blockIdx.x;
    const int chunk = bx >> 6;
    const int t = bx & 63;

    if (t >= lens[g_order[chunk * 128 + 127]]) return;

    const int tid = threadIdx.x;
    const int n0 = blockIdx.y * 128;
    const int dir = (n0 >= Gsz) ? 1 : 0;
    const float* __restrict__ W    = dir ? Wb : Wf;
    const float* __restrict__ bias = dir ? bb : bf;
    const int g0 = n0 - dir * Gsz;
    const int s  = dir ? (Ssz - 1 - t) : t;     // backward pre-reads reversed x

    const int tx = tid & 15;
    const int ty = tid >> 4;

    const int arow = tid >> 1;       // 0..127
    const int half = tid & 1;        // 0/1 -> k offset 0/4

    const int browB = g_order[chunk * 128 + arow];
    const float* aP = X + ((size_t)browB * Ssz + s) * Dsz + half * 4;
    const float* bP = W + (size_t)(g0 + arow) * Dsz + half * 4;

    ull acc2[8][4];
    #pragma unroll
    for (int i = 0; i < 8; i++)
        #pragma unroll
        for (int j = 0; j < 4; j++) acc2[i][j] = 0ULL;

    const int NK = (Dsz + 7) / 8;   // 38

    {
        float4 av = *(const float4*)aP;
        float4 bv = *(const float4*)bP;
        As[0][half*4+0][arow] = av.x; As[0][half*4+1][arow] = av.y;
        As[0][half*4+2][arow] = av.z; As[0][half*4+3][arow] = av.w;
        Bs[0][half*4+0][arow] = bv.x; Bs[0][half*4+1][arow] = bv.y;
        Bs[0][half*4+2][arow] = bv.z; Bs[0][half*4+3][arow] = bv.w;
    }
    __syncthreads();

    for (int it = 0; it < NK; it++) {
        const int buf = it & 1;
        float4 anx = make_float4(0.f, 0.f, 0.f, 0.f);
        float4 bnx = make_float4(0.f, 0.f, 0.f, 0.f);
        const bool has = (it + 1 < NK);
        if (has) {
            const int k0n = (it + 1) * 8;
            if (k0n + half * 4 < Dsz) {
                anx = *(const float4*)(aP + k0n);
                bnx = *(const float4*)(bP + k0n);
            }
        }

        #pragma unroll
        for (int kk = 0; kk < 8; kk++) {
            float4 a0 = *(const float4*)&As[buf][kk][ty*8];
            float4 a1 = *(const float4*)&As[buf][kk][ty*8+4];
            const double2* bd = (const double2*)&Bs[buf][kk][0];
            double2 b01 = bd[tx*2];
            double2 b23 = bd[tx*2+1];
            ull bb2[4] = { __double_as_longlong(b01.x), __double_as_longlong(b01.y),
                           __double_as_longlong(b23.x), __double_as_longlong(b23.y) };
            float a[8] = {a0.x, a0.y, a0.z, a0.w, a1.x, a1.y, a1.z, a1.w};
            #pragma unroll
            for (int i = 0; i < 8; i++) {
                ull ad; PACK2(ad, a[i]);
                #pragma unroll
                for (int j = 0; j < 4; j++)
                    FMA2(acc2[i][j], ad, bb2[j]);
            }
        }

        if (has) {
            __syncthreads();
            const int nb = buf ^ 1;
            As[nb][half*4+0][arow] = anx.x; As[nb][half*4+1][arow] = anx.y;
            As[nb][half*4+2][arow] = anx.z; As[nb][half*4+3][arow] = anx.w;
            Bs[nb][half*4+0][arow] = bnx.x; Bs[nb][half*4+1][arow] = bnx.y;
            Bs[nb][half*4+2][arow] = bnx.z; Bs[nb][half*4+3][arow] = bnx.w;
            __syncthreads();
        }
    }

    const float4 bv0 = *(const float4*)(bias + g0 + tx*8);
    const float4 bv1 = *(const float4*)(bias + g0 + tx*8 + 4);
    const float bb8[8] = {bv0.x, bv0.y, bv0.z, bv0.w, bv1.x, bv1.y, bv1.z, bv1.w};
    #pragma unroll
    for (int i = 0; i < 8; i++) {
        const size_t sb = (size_t)chunk * 128 + ty*8 + i;
        float* outp = g_GI + (((size_t)dir * Ssz + t) * Bsz + sb) * Gsz + g0 + tx*8;
        float o[8];
        #pragma unroll
        for (int j = 0; j < 4; j++) {
            o[2*j]   = f2lo(acc2[i][j]) + bb8[2*j];
            o[2*j+1] = f2hi(acc2[i][j]) + bb8[2*j+1];
        }
        *(float4*)outp       = make_float4(o[0], o[1], o[2], o[3]);
        *(float4*)(outp + 4) = make_float4(o[4], o[5], o[6], o[7]);
    }
}

// ---------------------------------------------------------------------------
// Kernel 2: GRU recurrence, f32x2, TMA weight ring — WARP-SPECIALIZED.
// 288 threads: warps 0..7 are consumers (identical code to the proven R10
// consumer path, producer branch removed); warp 8 is a dedicated producer
// running prologue + refill loop, then exits. Consumer step barrier is the
// named barrier 1 (256 threads); the producer never joins it. Ring protocol
// (full=1 tx-arrive, empty=8 consumer arrives, phase parity per stage round)
// is IDENTICAL to R10. Arithmetic identical to R10 (libm tanhf).
// Grid 256; bid<148 ? bid : 403-bid pairs long+short tasks on the same SM.
// ---------------------------------------------------------------------------
__global__ __launch_bounds__(288, 2) void k_gru(
    const float* __restrict__ bhh_f, const float* __restrict__ bhh_b,
    const int* __restrict__ lens)
{
    extern __shared__ __align__(128) unsigned char dsm[];
    float* hA = (float*)(dsm + OFF_HA);
    float* hB = (float*)(dsm + OFF_HB);
    int*  slen = (int*)(dsm + OFF_SLEN);
    int*  srow = (int*)(dsm + OFF_SROW);
    const uint32_t mbF = smem_u32(dsm + OFF_MBF);
    const uint32_t mbE = smem_u32(dsm + OFF_MBE);
    const uint32_t wst = smem_u32(dsm + OFF_W);

    const int tid = threadIdx.x;
    const int lane0 = ((tid & 31) == 0);
    const int bid = blockIdx.x;
    const int r   = (bid < 148) ? bid : (403 - bid);   // steps-desc task rank
    const int dir = r & 1;
    const int grp = 127 - (r >> 1);

    const float* __restrict__ bhh = dir ? bhh_b : bhh_f;
    const float* __restrict__ wsrc0 = g_W4 + (size_t)dir * (Hsz/4) * Gsz * 4;

    if (tid < Rr) {
        const int b = g_order[grp * Rr + tid];
        srow[tid] = b;
        slen[tid] = lens[b];
    }
    if (tid == 0) {
        #pragma unroll
        for (int ss = 0; ss < NST; ss++) {
            mbar_init(mbF + ss * 8, 1);   // TMA tx completion
            mbar_init(mbE + ss * 8, 8);   // one arrive per consumer warp
        }
    }
    for (int i = tid; i < Rr * Hsz; i += 288) hA[i] = 0.f;
    __syncthreads();   // all 288 threads; barriers/h/slen visible to everyone

    int maxT = 0;
    #pragma unroll
    for (int q = 0; q < Rr; q++) maxT = max(maxT, slen[q]);

    const int total = (maxT - 1) * 128;   // k4-slabs consumed (t=0 skipped)

    // ---- producer warp (tid 256..287): prologue fills + refill loop, exit ----
    if (tid >= 256) {
        if (tid == 256) {
            const int nf = total < NST ? total : NST;
            for (int i = 0; i < nf; i++) {
                mbar_expect_tx(mbF + i * 8, WBYTES);
                bulk_g2s(wst + i * WBYTES, wsrc0 + (size_t)i * (Gsz * 4),
                         WBYTES, mbF + i * 8);
            }
            int st = 0, ph = 0;
            for (int c = 0; c + NST < total; c++) {
                // wait until all 8 consumer warps released stage st (round c/NST)
                mbar_wait(mbE + st * 8, ph);
                mbar_expect_tx(mbF + st * 8, WBYTES);
                bulk_g2s(wst + st * WBYTES,
                         wsrc0 + (size_t)((c + NST) & 127) * (Gsz * 4),
                         WBYTES, mbF + st * 8);
                if (++st == NST) { st = 0; ph ^= 1; }
            }
        }
        return;   // producer warp done; consumers use named barrier 1 only
    }

    // ---- consumer warps (tid 0..255) ----
    const int j0 = tid;
    const int j1 = tid + 256;

    const float bR0 = bhh[j0], bZ0 = bhh[j0 + Hsz], bN0 = bhh[j0 + 2*Hsz];
    const float bR1 = bhh[j1], bZ1 = bhh[j1 + Hsz], bN1 = bhh[j1 + 2*Hsz];

    float sum0[Rr], sum1[Rr];
    #pragma unroll
    for (int q = 0; q < Rr; q++) { sum0[q] = 0.f; sum1[q] = 0.f; }

    float* hcur = hA;
    float* hnxt = hB;
    int st = 0;    // stage = consumed-slab % NST
    int ph = 0;    // phase = (consumed-slab / NST) & 1

    for (int t = 0; t < maxT; t++) {
        ull aR0[4], aZ0[4], aN0[4], aR1[4], aZ1[4], aN1[4];
        #pragma unroll
        for (int p = 0; p < 4; p++) {
            aR0[p] = 0ULL; aZ0[p] = 0ULL; aN0[p] = 0ULL;
            aR1[p] = 0ULL; aZ1[p] = 0ULL; aN1[p] = 0ULL;
        }

        if (t > 0) {
            const double2* hb = (const double2*)hcur;   // [pair*256 + k/2]
            #pragma unroll 1
            for (int k4 = 0; k4 < Hsz / 4; k4++) {
                mbar_wait(mbF + st * 8, ph);

                const float4* ws = (const float4*)(dsm + OFF_W + st * WBYTES);
                const float4 vr0 = ws[j0];
                const float4 vz0 = ws[j0 + Hsz];
                const float4 vn0 = ws[j0 + 2*Hsz];
                const float4 vr1 = ws[j1];
                const float4 vz1 = ws[j1 + Hsz];
                const float4 vn1 = ws[j1 + 2*Hsz];

                // weights for this stage are in registers -> release the stage
                if (lane0) mbar_arrive(mbE + st * 8);

                ull h0[4], h1[4], h2[4], h3[4];
                #pragma unroll
                for (int p = 0; p < 4; p++) {
                    double2 dA = hb[p * 256 + 2*k4];
                    double2 dB = hb[p * 256 + 2*k4 + 1];
                    h0[p] = __double_as_longlong(dA.x);
                    h1[p] = __double_as_longlong(dA.y);
                    h2[p] = __double_as_longlong(dB.x);
                    h3[p] = __double_as_longlong(dB.y);
                }

#define DOKK(C, HARR) do {                                                     \
    ull w0r, w0z, w0n, w1r, w1z, w1n;                                          \
    PACK2(w0r, vr0.C); PACK2(w0z, vz0.C); PACK2(w0n, vn0.C);                   \
    PACK2(w1r, vr1.C); PACK2(w1z, vz1.C); PACK2(w1n, vn1.C);                   \
    _Pragma("unroll")                                                          \
    for (int p = 0; p < 4; p++) {                                              \
        FMA2(aR0[p], w0r, HARR[p]); FMA2(aZ0[p], w0z, HARR[p]);                \
        FMA2(aN0[p], w0n, HARR[p]);                                            \
        FMA2(aR1[p], w1r, HARR[p]); FMA2(aZ1[p], w1z, HARR[p]);                \
        FMA2(aN1[p], w1n, HARR[p]);                                            \
    } } while (0)

                DOKK(x, h0);
                DOKK(y, h1);
                DOKK(z, h2);
                DOKK(w, h3);
#undef DOKK

                if (++st == NST) { st = 0; ph ^= 1; }
            }
        }

        // epilogue: gates + h update + masked accumulation (R10 arithmetic)
        #pragma unroll
        for (int q = 0; q < Rr; q++) {
            const int p = q >> 1;
            const int cc = q & 1;
            const float* __restrict__ gi =
                g_GI + (((size_t)dir * Ssz + t) * Bsz + grp * Rr + q) * Gsz;
            const float m = (t < slen[q]) ? 1.f : 0.f;
            {
                const float aR = cc ? f2hi(aR0[p]) : f2lo(aR0[p]);
                const float aZ = cc ? f2hi(aZ0[p]) : f2lo(aZ0[p]);
                const float aN = cc ? f2hi(aN0[p]) : f2lo(aN0[p]);
                float rg = sigm(gi[j0]          + aR + bR0);
                float zg = sigm(gi[j0 + Hsz]    + aZ + bZ0);
                float ng = tanhf(gi[j0 + 2*Hsz] + rg * (aN + bN0));
                float hv = hcur[(p * Hsz + j0) * 2 + cc];
                float hn = ng + zg * (hv - ng);    // (1-z)*n + z*h
                hnxt[(p * Hsz + j0) * 2 + cc] = hn;
                sum0[q] += hn * m;
            }
            {
                const float aR = cc ? f2hi(aR1[p]) : f2lo(aR1[p]);
                const float aZ = cc ? f2hi(aZ1[p]) : f2lo(aZ1[p]);
                const float aN = cc ? f2hi(aN1[p]) : f2lo(aN1[p]);
                float rg = sigm(gi[j1]          + aR + bR1);
                float zg = sigm(gi[j1 + Hsz]    + aZ + bZ1);
                float ng = tanhf(gi[j1 + 2*Hsz] + rg * (aN + bN1));
                float hv = hcur[(p * Hsz + j1) * 2 + cc];
                float hn = ng + zg * (hv - ng);
                hnxt[(p * Hsz + j1) * 2 + cc] = hn;
                sum1[q] += hn * m;
            }
        }
        BAR_CONS();   // consumer warps only (named barrier 1, 256 threads)
        float* tp = hcur; hcur = hnxt; hnxt = tp;
    }

    #pragma unroll
    for (int q = 0; q < Rr; q++) {
        g_part[((size_t)dir * Bsz + srow[q]) * Hsz + j0] = sum0[q];
        g_part[((size_t)dir * Bsz + srow[q]) * Hsz + j1] = sum1[q];
    }
}

// ---------------------------------------------------------------------------
// Kernel 3: avg = 0.5*(sum_f + sum_b)/len; mu/sigma heads; reparam sample.
// Output layout: [final (B*Z) | mu (B*Z) | sigma (B*Z)]
// ---------------------------------------------------------------------------
__global__ __launch_bounds__(128) void k_head(
    const float* __restrict__ Wmu, const float* __restrict__ bmu,
    const float* __restrict__ Wsg, const float* __restrict__ bsg,
    const float* __restrict__ eps, const int* __restrict__ lens,
    float* __restrict__ out)
{
    __shared__ float avg[Hsz];
    const int b = blockIdx.x;
    const int tid = threadIdx.x;
    const float inv = 0.5f / (float)lens[b];   // mask.sum(0) == len
    for (int i = tid; i < Hsz; i += 128)
        avg[i] = (g_part[(size_t)b * Hsz + i] +
                  g_part[((size_t)Bsz + b) * Hsz + i]) * inv;
    __syncthreads();

    const float4* a4 = (const float4*)avg;
    const float4* wm = (const float4*)(Wmu + (size_t)tid * Hsz);
    const float4* ws = (const float4*)(Wsg + (size_t)tid * Hsz);
    float sm = 0.f, ss = 0.f;
    #pragma unroll 4
    for (int i = 0; i < Hsz / 4; i++) {
        float4 a = a4[i];
        sm = dot4(wm[i], a, sm);
        ss = dot4(ws[i], a, ss);
    }
    sm += bmu[tid];
    ss += bsg[tid];
    float mu = (sm >= 0.f) ? sm : 0.2f * sm;   // leaky relu 0.2
    float ls = (ss >= 0.f) ? ss : 0.2f * ss;
    float sg = expf(ls);
    float fin = fmaf(eps[(size_t)b * Zsz + tid], sg, mu);
    out[(size_t)b * Zsz + tid]              = fin;
    out[((size_t)Bsz + b) * Zsz + tid]      = mu;
    out[((size_t)2 * Bsz + b) * Zsz + tid]  = sg;
}

extern "C" void kernel_launch(void* const* d_in, const int* in_sizes, int n_in,
                              void* d_out, int out_size)
{
    const float* text  = (const float*)d_in[0];
    const int*   lens  = (const int*)  d_in[1];
    const float* Wih_f = (const float*)d_in[2];
    const float* Whh_f = (const float*)d_in[3];
    const float* bih_f = (const float*)d_in[4];
    const float* bhh_f = (const float*)d_in[5];
    const float* Wih_b = (const float*)d_in[6];
    const float* Whh_b = (const float*)d_in[7];
    const float* bih_b = (const float*)d_in[8];
    const float* bhh_b = (const float*)d_in[9];
    const float* W_mu  = (const float*)d_in[10];
    const float* b_mu  = (const float*)d_in[11];
    const float* W_sig = (const float*)d_in[12];
    const float* b_sig = (const float*)d_in[13];
    const float* eps   = (const float*)d_in[14];
    float* out = (float*)d_out;

    cudaFuncSetAttribute(k_gru, cudaFuncAttributeMaxDynamicSharedMemorySize, SMEM_GRU);

    // 0) length sort + packed weight layout (one-time, cheap)
    k_sort<<<1, Bsz>>>(lens);
    {
        const size_t total = (size_t)2 * (Hsz/4) * Gsz * 4;
        k_wt4<<<(unsigned)((total + 255) / 256), 256>>>(Whh_f, Whh_b);
    }
    // 1) GI (t-major over sorted rows; dead tiles skipped)
    k_gi_gemm<<<dim3(8 * Ssz, (2 * Gsz) / 128), 256>>>(
        text, Wih_f, bih_f, Wih_b, bih_b, lens);
    // 2) GRU scan (warp-specialized producer, R10 ring protocol + arithmetic)
    k_gru<<<256, 288, SMEM_GRU>>>(bhh_f, bhh_b, lens);
    // 3) Average + VAE heads + reparameterized sample
    k_head<<<Bsz, 128>>>(W_mu, b_mu, W_sig, b_sig, eps, lens, out);
}

// round 17
// speedup vs baseline: 6.8404x; 1.3317x over previous
#include <cuda_runtime.h>
#include <math.h>
#include <stddef.h>
#include <stdint.h>

namespace {
constexpr int Bsz = 1024;
constexpr int Ssz = 64;
constexpr int Dsz = 300;
constexpr int Hsz = 512;
constexpr int Gsz = 1536;   // 3H
constexpr int Zsz = 128;
constexpr int MR  = Bsz * Ssz;   // 65536
constexpr int Rr  = 8;           // batch rows per GRU CTA (4 f32x2 pairs)

constexpr int NST    = 5;                       // weight pipeline stages
constexpr int WBYTES = Gsz * 4 * 4;             // 24576 B per k4 slab
constexpr int OFF_W    = 0;
constexpr int OFF_HA   = NST * WBYTES;          // 122880
constexpr int OFF_HB   = OFF_HA + Rr * Hsz * 4; // 139264
constexpr int OFF_MBF  = OFF_HB + Rr * Hsz * 4; // 155648 (full barriers, 5x8B)
constexpr int OFF_MBE  = OFF_MBF + NST * 8;     // empty barriers (5x8B)
constexpr int OFF_SLEN = OFF_MBE + NST * 8;
constexpr int OFF_SROW = OFF_SLEN + Rr * 4;
constexpr int SMEM_GRU = OFF_SROW + Rr * 4 + 64;   // ~152.2 KB -> 1 CTA/SM
}

typedef unsigned long long ull;

// Scratch (allocation-free rule: __device__ globals)
__device__ float g_GI[(size_t)2 * MR * Gsz];          // [dir][t][sorted_b][3H]
__device__ float g_part[(size_t)2 * Bsz * Hsz];       // masked hidden sums per direction
__device__ float g_W4[(size_t)2 * (Hsz/4) * Gsz * 4]; // packed Whh: [dir][k/4][g][kk]
__device__ int   g_order[Bsz];                        // rows sorted by length (ascending)

// packed f32x2 helpers (FFMA2 — 2 exact fp32 FMAs per instruction)
#define FMA2(acc, a, b) \
    asm("fma.rn.f32x2 %0, %1, %2, %0;" : "+l"(acc) : "l"(a), "l"(b))
#define PACK2(d, s) \
    asm("mov.b64 %0, {%1, %1};" : "=l"(d) : "f"(s))

// consumer-only step barrier (named barrier 1, 256 threads = warps 0..7)
#define BAR_CONS() asm volatile("bar.sync 1, 256;" ::: "memory")

__device__ __forceinline__ float f2lo(ull u) { return __uint_as_float((unsigned)u); }
__device__ __forceinline__ float f2hi(ull u) { return __uint_as_float((unsigned)(u >> 32)); }

__device__ __forceinline__ uint32_t smem_u32(const void* p) {
    return (uint32_t)__cvta_generic_to_shared(p);
}

__device__ __forceinline__ void mbar_init(uint32_t mbar, uint32_t cnt) {
    asm volatile("mbarrier.init.shared.b64 [%0], %1;" :: "r"(mbar), "r"(cnt) : "memory");
}
__device__ __forceinline__ void mbar_expect_tx(uint32_t mbar, uint32_t bytes) {
    asm volatile("mbarrier.arrive.expect_tx.shared.b64 _, [%0], %1;"
                 :: "r"(mbar), "r"(bytes) : "memory");
}
__device__ __forceinline__ void mbar_arrive(uint32_t mbar) {
    asm volatile("mbarrier.arrive.shared.b64 _, [%0];" :: "r"(mbar) : "memory");
}
__device__ __forceinline__ void mbar_wait(uint32_t mbar, uint32_t phase) {
    uint32_t done;
    asm volatile("{\n\t.reg .pred p;\n\t"
        "mbarrier.try_wait.parity.acquire.cta.shared::cta.b64 p, [%1], %2;\n\t"
        "selp.b32 %0, 1, 0, p;\n\t}"
        : "=r"(done) : "r"(mbar), "r"(phase) : "memory");
    while (!done) {
        asm volatile("{\n\t.reg .pred p;\n\t"
            "mbarrier.try_wait.parity.acquire.cta.shared::cta.b64 p, [%1], %2, 0x989680;\n\t"
            "selp.b32 %0, 1, 0, p;\n\t}"
            : "=r"(done) : "r"(mbar), "r"(phase) : "memory");
    }
}
__device__ __forceinline__ void bulk_g2s(uint32_t dst, const void* src,
                                         uint32_t bytes, uint32_t mbar) {
    asm volatile(
        "cp.async.bulk.shared::cluster.global.mbarrier::complete_tx::bytes "
        "[%0], [%1], %2, [%3];"
        :: "r"(dst), "l"(src), "r"(bytes), "r"(mbar) : "memory");
}

__device__ __forceinline__ float dot4(float4 w, float4 h, float a) {
    a = fmaf(w.x, h.x, a);
    a = fmaf(w.y, h.y, a);
    a = fmaf(w.z, h.z, a);
    a = fmaf(w.w, h.w, a);
    return a;
}

__device__ __forceinline__ float sigm(float x) {
    return 1.f / (1.f + __expf(-x));
}

// ---------------------------------------------------------------------------
// Sort rows by length (counting sort, single block). Output values are
// permutation-invariant within equal-length bins.
// ---------------------------------------------------------------------------
__global__ void k_sort(const int* __restrict__ lens)
{
    __shared__ int hist[Ssz + 1];
    __shared__ int off[Ssz + 2];
    const int tid = threadIdx.x;
    if (tid <= Ssz) hist[tid] = 0;
    __syncthreads();
    const int l = lens[tid];
    atomicAdd(&hist[l], 1);
    __syncthreads();
    if (tid == 0) {
        int run = 0;
        for (int i = 1; i <= Ssz; i++) { off[i] = run; run += hist[i]; }
    }
    __syncthreads();
    int pos = atomicAdd(&off[l], 1);
    g_order[pos] = tid;
}

// ---------------------------------------------------------------------------
// Repack Whh -> W4[dir][k/4][g][kk]
// ---------------------------------------------------------------------------
__global__ __launch_bounds__(256) void k_wt4(
    const float* __restrict__ Whh_f, const float* __restrict__ Whh_b)
{
    size_t idx = (size_t)blockIdx.x * 256 + threadIdx.x;
    const size_t per = (size_t)(Hsz/4) * Gsz * 4;
    if (idx >= 2 * per) return;
    const int dir = (int)(idx / per);
    size_t rem = idx - (size_t)dir * per;
    const int kk = (int)(rem & 3);
    size_t r2 = rem >> 2;
    const int g  = (int)(r2 % Gsz);
    const int k4 = (int)(r2 / Gsz);
    const float* W = dir ? Whh_b : Whh_f;
    g_W4[idx] = W[(size_t)g * Hsz + k4 * 4 + kk];
}

// ---------------------------------------------------------------------------
// Kernel 1: GI[dir][t][sorted_b][g] = x[order(sb)][dir? 63-t : t] @ Wih.T + b.
// t-major layout over length-sorted rows; tiles with t >= chunk-max-length
// exit immediately. 128x128x8 tiles, 256 threads, 8x8 microtile (f32x2).
// ---------------------------------------------------------------------------
__global__ __launch_bounds__(256) void k_gi_gemm(
    const float* __restrict__ X,
    const float* __restrict__ Wf, const float* __restrict__ bf,
    const float* __restrict__ Wb, const float* __restrict__ bb,
    const int* __restrict__ lens)
{
    __shared__ __align__(16) float As[2][8][128];
    __shared__ __align__(16) float Bs[2][8][128];

    const int bx = blockIdx.x;
    const int chunk = bx >> 6;
    const int t = bx & 63;

    if (t >= lens[g_order[chunk * 128 + 127]]) return;

    const int tid = threadIdx.x;
    const int n0 = blockIdx.y * 128;
    const int dir = (n0 >= Gsz) ? 1 : 0;
    const float* __restrict__ W    = dir ? Wb : Wf;
    const float* __restrict__ bias = dir ? bb : bf;
    const int g0 = n0 - dir * Gsz;
    const int s  = dir ? (Ssz - 1 - t) : t;     // backward pre-reads reversed x

    const int tx = tid & 15;
    const int ty = tid >> 4;

    const int arow = tid >> 1;       // 0..127
    const int half = tid & 1;        // 0/1 -> k offset 0/4

    const int browB = g_order[chunk * 128 + arow];
    const float* aP = X + ((size_t)browB * Ssz + s) * Dsz + half * 4;
    const float* bP = W + (size_t)(g0 + arow) * Dsz + half * 4;

    ull acc2[8][4];
    #pragma unroll
    for (int i = 0; i < 8; i++)
        #pragma unroll
        for (int j = 0; j < 4; j++) acc2[i][j] = 0ULL;

    const int NK = (Dsz + 7) / 8;   // 38

    {
        float4 av = *(const float4*)aP;
        float4 bv = *(const float4*)bP;
        As[0][half*4+0][arow] = av.x; As[0][half*4+1][arow] = av.y;
        As[0][half*4+2][arow] = av.z; As[0][half*4+3][arow] = av.w;
        Bs[0][half*4+0][arow] = bv.x; Bs[0][half*4+1][arow] = bv.y;
        Bs[0][half*4+2][arow] = bv.z; Bs[0][half*4+3][arow] = bv.w;
    }
    __syncthreads();

    for (int it = 0; it < NK; it++) {
        const int buf = it & 1;
        float4 anx = make_float4(0.f, 0.f, 0.f, 0.f);
        float4 bnx = make_float4(0.f, 0.f, 0.f, 0.f);
        const bool has = (it + 1 < NK);
        if (has) {
            const int k0n = (it + 1) * 8;
            if (k0n + half * 4 < Dsz) {
                anx = *(const float4*)(aP + k0n);
                bnx = *(const float4*)(bP + k0n);
            }
        }

        #pragma unroll
        for (int kk = 0; kk < 8; kk++) {
            float4 a0 = *(const float4*)&As[buf][kk][ty*8];
            float4 a1 = *(const float4*)&As[buf][kk][ty*8+4];
            const double2* bd = (const double2*)&Bs[buf][kk][0];
            double2 b01 = bd[tx*2];
            double2 b23 = bd[tx*2+1];
            ull bb2[4] = { __double_as_longlong(b01.x), __double_as_longlong(b01.y),
                           __double_as_longlong(b23.x), __double_as_longlong(b23.y) };
            float a[8] = {a0.x, a0.y, a0.z, a0.w, a1.x, a1.y, a1.z, a1.w};
            #pragma unroll
            for (int i = 0; i < 8; i++) {
                ull ad; PACK2(ad, a[i]);
                #pragma unroll
                for (int j = 0; j < 4; j++)
                    FMA2(acc2[i][j], ad, bb2[j]);
            }
        }

        if (has) {
            __syncthreads();
            const int nb = buf ^ 1;
            As[nb][half*4+0][arow] = anx.x; As[nb][half*4+1][arow] = anx.y;
            As[nb][half*4+2][arow] = anx.z; As[nb][half*4+3][arow] = anx.w;
            Bs[nb][half*4+0][arow] = bnx.x; Bs[nb][half*4+1][arow] = bnx.y;
            Bs[nb][half*4+2][arow] = bnx.z; Bs[nb][half*4+3][arow] = bnx.w;
            __syncthreads();
        }
    }

    const float4 bv0 = *(const float4*)(bias + g0 + tx*8);
    const float4 bv1 = *(const float4*)(bias + g0 + tx*8 + 4);
    const float bb8[8] = {bv0.x, bv0.y, bv0.z, bv0.w, bv1.x, bv1.y, bv1.z, bv1.w};
    #pragma unroll
    for (int i = 0; i < 8; i++) {
        const size_t sb = (size_t)chunk * 128 + ty*8 + i;
        float* outp = g_GI + (((size_t)dir * Ssz + t) * Bsz + sb) * Gsz + g0 + tx*8;
        float o[8];
        #pragma unroll
        for (int j = 0; j < 4; j++) {
            o[2*j]   = f2lo(acc2[i][j]) + bb8[2*j];
            o[2*j+1] = f2hi(acc2[i][j]) + bb8[2*j+1];
        }
        *(float4*)outp       = make_float4(o[0], o[1], o[2], o[3]);
        *(float4*)(outp + 4) = make_float4(o[4], o[5], o[6], o[7]);
    }
}

// ---------------------------------------------------------------------------
// Kernel 2: PERSISTENT GRU. Grid 148 (1 CTA/SM), 288 threads.
// CTA b runs task rank b; CTAs b>=40 additionally run rank 295-b afterwards
// (ranks steps-descending; per-CTA load ~54-64 step-units, placement-free).
// Warp 8 = producer: streams the CONCATENATION of both tasks' weight-slab
// sequences through one continuous 5-stage full/empty mbarrier ring (task
// totals are multiples of 128 slabs, so `& 127` addressing is seamless).
// Warps 0..7 = consumers: identical R15 consumer path; (st, ph) persist
// across the task boundary. Epilogue batches all 48 GI loads (regs are free
// at 1 CTA/SM). Arithmetic identical to R15 (libm tanhf, same op order).
// ---------------------------------------------------------------------------
__global__ __launch_bounds__(288, 1) void k_gru(
    const float* __restrict__ bhh_f, const float* __restrict__ bhh_b,
    const int* __restrict__ lens)
{
    extern __shared__ __align__(128) unsigned char dsm[];
    float* hA = (float*)(dsm + OFF_HA);
    float* hB = (float*)(dsm + OFF_HB);
    int*  slen = (int*)(dsm + OFF_SLEN);
    int*  srow = (int*)(dsm + OFF_SROW);
    const uint32_t mbF = smem_u32(dsm + OFF_MBF);
    const uint32_t mbE = smem_u32(dsm + OFF_MBE);
    const uint32_t wst = smem_u32(dsm + OFF_W);

    const int tid = threadIdx.x;
    const int lane0 = ((tid & 31) == 0);
    const int b = blockIdx.x;
    const int nt = (b < 40) ? 1 : 2;   // tasks this CTA runs

    if (tid == 0) {
        #pragma unroll
        for (int ss = 0; ss < NST; ss++) {
            mbar_init(mbF + ss * 8, 1);   // TMA tx completion
            mbar_init(mbE + ss * 8, 8);   // one arrive per consumer warp
        }
    }
    // task 0 setup (srow/slen) done pre-sync so producer init is also covered
    if (tid < Rr) {
        const int grp0 = 127 - (b >> 1);
        const int row = g_order[grp0 * Rr + tid];
        srow[tid] = row;
        slen[tid] = lens[row];
    }
    for (int i = tid; i < Rr * Hsz; i += 288) hA[i] = 0.f;
    __syncthreads();   // all 288: barriers + task-0 smem visible

    // ---- producer warp: concatenated slab stream over this CTA's tasks ----
    if (tid >= 256) {
        if (tid == 256) {
            long tot[2] = {0, 0};
            const float* src[2] = {nullptr, nullptr};
            for (int k = 0; k < nt; k++) {
                const int rk = (k == 0) ? b : (295 - b);
                const int dirk = rk & 1;
                const int grpk = 127 - (rk >> 1);
                int mT = 0;
                for (int i = 0; i < Rr; i++) {
                    const int l = lens[g_order[grpk * Rr + i]];
                    mT = max(mT, l);
                }
                tot[k] = (long)(mT - 1) * 128;
                src[k] = g_W4 + (size_t)dirk * (Hsz/4) * Gsz * 4;
            }
            const long totAll = tot[0] + tot[1];
            const long nf = totAll < NST ? totAll : NST;
            for (long i = 0; i < nf; i++) {
                const float* s = (i < tot[0]) ? src[0] : src[1];
                mbar_expect_tx(mbF + (int)i * 8, WBYTES);
                bulk_g2s(wst + (uint32_t)i * WBYTES,
                         s + (size_t)(i & 127) * (Gsz * 4), WBYTES, mbF + (int)i * 8);
            }
            int st = 0, ph = 0;
            for (long c = 0; c + NST < totAll; c++) {
                const long x = c + NST;
                const float* s = (x < tot[0]) ? src[0] : src[1];
                mbar_wait(mbE + st * 8, ph);
                mbar_expect_tx(mbF + st * 8, WBYTES);
                bulk_g2s(wst + st * WBYTES,
                         s + (size_t)(x & 127) * (Gsz * 4), WBYTES, mbF + st * 8);
                if (++st == NST) { st = 0; ph ^= 1; }
            }
        }
        return;   // producer warp done; consumers use named barrier 1 only
    }

    // ---- consumer warps (tid 0..255) ----
    const int j0 = tid;
    const int j1 = tid + 256;

    int st = 0;   // stage/phase persist across tasks (continuous slab stream)
    int ph = 0;

    for (int k = 0; k < nt; k++) {
        const int rk = (k == 0) ? b : (295 - b);
        const int dir = rk & 1;
        const int grp = 127 - (rk >> 1);
        const float* __restrict__ bhh = dir ? bhh_b : bhh_f;

        if (k > 0) {
            BAR_CONS();   // protect task-0 srow/slen + h against rewrite
            if (tid < Rr) {
                const int row = g_order[grp * Rr + tid];
                srow[tid] = row;
                slen[tid] = lens[row];
            }
            for (int i = tid; i < Rr * Hsz; i += 256) hA[i] = 0.f;
            BAR_CONS();
        }

        int maxT = 0;
        #pragma unroll
        for (int q = 0; q < Rr; q++) maxT = max(maxT, slen[q]);

        const float bR0 = bhh[j0], bZ0 = bhh[j0 + Hsz], bN0 = bhh[j0 + 2*Hsz];
        const float bR1 = bhh[j1], bZ1 = bhh[j1 + Hsz], bN1 = bhh[j1 + 2*Hsz];

        float sum0[Rr], sum1[Rr];
        #pragma unroll
        for (int q = 0; q < Rr; q++) { sum0[q] = 0.f; sum1[q] = 0.f; }

        float* hcur = hA;
        float* hnxt = hB;

        for (int t = 0; t < maxT; t++) {
            ull aR0[4], aZ0[4], aN0[4], aR1[4], aZ1[4], aN1[4];
            #pragma unroll
            for (int p = 0; p < 4; p++) {
                aR0[p] = 0ULL; aZ0[p] = 0ULL; aN0[p] = 0ULL;
                aR1[p] = 0ULL; aZ1[p] = 0ULL; aN1[p] = 0ULL;
            }

            if (t > 0) {
                const double2* hb = (const double2*)hcur;   // [pair*256 + k/2]
                #pragma unroll 1
                for (int k4 = 0; k4 < Hsz / 4; k4++) {
                    mbar_wait(mbF + st * 8, ph);

                    const float4* ws = (const float4*)(dsm + OFF_W + st * WBYTES);
                    const float4 vr0 = ws[j0];
                    const float4 vz0 = ws[j0 + Hsz];
                    const float4 vn0 = ws[j0 + 2*Hsz];
                    const float4 vr1 = ws[j1];
                    const float4 vz1 = ws[j1 + Hsz];
                    const float4 vn1 = ws[j1 + 2*Hsz];

                    // stage weights in registers -> release the stage
                    if (lane0) mbar_arrive(mbE + st * 8);

                    ull h0[4], h1[4], h2[4], h3[4];
                    #pragma unroll
                    for (int p = 0; p < 4; p++) {
                        double2 dA = hb[p * 256 + 2*k4];
                        double2 dB = hb[p * 256 + 2*k4 + 1];
                        h0[p] = __double_as_longlong(dA.x);
                        h1[p] = __double_as_longlong(dA.y);
                        h2[p] = __double_as_longlong(dB.x);
                        h3[p] = __double_as_longlong(dB.y);
                    }

#define DOKK(C, HARR) do {                                                     \
    ull w0r, w0z, w0n, w1r, w1z, w1n;                                          \
    PACK2(w0r, vr0.C); PACK2(w0z, vz0.C); PACK2(w0n, vn0.C);                   \
    PACK2(w1r, vr1.C); PACK2(w1z, vz1.C); PACK2(w1n, vn1.C);                   \
    _Pragma("unroll")                                                          \
    for (int p = 0; p < 4; p++) {                                              \
        FMA2(aR0[p], w0r, HARR[p]); FMA2(aZ0[p], w0z, HARR[p]);                \
        FMA2(aN0[p], w0n, HARR[p]);                                            \
        FMA2(aR1[p], w1r, HARR[p]); FMA2(aZ1[p], w1z, HARR[p]);                \
        FMA2(aN1[p], w1n, HARR[p]);                                            \
    } } while (0)

                    DOKK(x, h0);
                    DOKK(y, h1);
                    DOKK(z, h2);
                    DOKK(w, h3);
#undef DOKK

                    if (++st == NST) { st = 0; ph ^= 1; }
                }
            }

            // epilogue: batch ALL 48 GI loads first (MLP 48), then gates
            float gv[Rr][6];
            {
                const float* __restrict__ gibase =
                    g_GI + (((size_t)dir * Ssz + t) * Bsz + grp * Rr) * Gsz;
                #pragma unroll
                for (int q = 0; q < Rr; q++) {
                    const float* __restrict__ gi = gibase + (size_t)q * Gsz;
                    gv[q][0] = gi[j0];
                    gv[q][1] = gi[j0 + Hsz];
                    gv[q][2] = gi[j0 + 2*Hsz];
                    gv[q][3] = gi[j1];
                    gv[q][4] = gi[j1 + Hsz];
                    gv[q][5] = gi[j1 + 2*Hsz];
                }
            }
            #pragma unroll
            for (int q = 0; q < Rr; q++) {
                const int p = q >> 1;
                const int cc = q & 1;
                const float m = (t < slen[q]) ? 1.f : 0.f;
                {
                    const float aR = cc ? f2hi(aR0[p]) : f2lo(aR0[p]);
                    const float aZ = cc ? f2hi(aZ0[p]) : f2lo(aZ0[p]);
                    const float aN = cc ? f2hi(aN0[p]) : f2lo(aN0[p]);
                    float rg = sigm(gv[q][0] + aR + bR0);
                    float zg = sigm(gv[q][1] + aZ + bZ0);
                    float ng = tanhf(gv[q][2] + rg * (aN + bN0));
                    float hv = hcur[(p * Hsz + j0) * 2 + cc];
                    float hn = ng + zg * (hv - ng);    // (1-z)*n + z*h
                    hnxt[(p * Hsz + j0) * 2 + cc] = hn;
                    sum0[q] += hn * m;
                }
                {
                    const float aR = cc ? f2hi(aR1[p]) : f2lo(aR1[p]);
                    const float aZ = cc ? f2hi(aZ1[p]) : f2lo(aZ1[p]);
                    const float aN = cc ? f2hi(aN1[p]) : f2lo(aN1[p]);
                    float rg = sigm(gv[q][3] + aR + bR1);
                    float zg = sigm(gv[q][4] + aZ + bZ1);
                    float ng = tanhf(gv[q][5] + rg * (aN + bN1));
                    float hv = hcur[(p * Hsz + j1) * 2 + cc];
                    float hn = ng + zg * (hv - ng);
                    hnxt[(p * Hsz + j1) * 2 + cc] = hn;
                    sum1[q] += hn * m;
                }
            }
            BAR_CONS();   // consumer warps only (named barrier 1, 256 threads)
            float* tp = hcur; hcur = hnxt; hnxt = tp;
        }

        #pragma unroll
        for (int q = 0; q < Rr; q++) {
            g_part[((size_t)dir * Bsz + srow[q]) * Hsz + j0] = sum0[q];
            g_part[((size_t)dir * Bsz + srow[q]) * Hsz + j1] = sum1[q];
        }
    }
}

// ---------------------------------------------------------------------------
// Kernel 3: avg = 0.5*(sum_f + sum_b)/len; mu/sigma heads; reparam sample.
// Output layout: [final (B*Z) | mu (B*Z) | sigma (B*Z)]
// ---------------------------------------------------------------------------
__global__ __launch_bounds__(128) void k_head(
    const float* __restrict__ Wmu, const float* __restrict__ bmu,
    const float* __restrict__ Wsg, const float* __restrict__ bsg,
    const float* __restrict__ eps, const int* __restrict__ lens,
    float* __restrict__ out)
{
    __shared__ float avg[Hsz];
    const int b = blockIdx.x;
    const int tid = threadIdx.x;
    const float inv = 0.5f / (float)lens[b];   // mask.sum(0) == len
    for (int i = tid; i < Hsz; i += 128)
        avg[i] = (g_part[(size_t)b * Hsz + i] +
                  g_part[((size_t)Bsz + b) * Hsz + i]) * inv;
    __syncthreads();

    const float4* a4 = (const float4*)avg;
    const float4* wm = (const float4*)(Wmu + (size_t)tid * Hsz);
    const float4* ws = (const float4*)(Wsg + (size_t)tid * Hsz);
    float sm = 0.f, ss = 0.f;
    #pragma unroll 4
    for (int i = 0; i < Hsz / 4; i++) {
        float4 a = a4[i];
        sm = dot4(wm[i], a, sm);
        ss = dot4(ws[i], a, ss);
    }
    sm += bmu[tid];
    ss += bsg[tid];
    float mu = (sm >= 0.f) ? sm : 0.2f * sm;   // leaky relu 0.2
    float ls = (ss >= 0.f) ? ss : 0.2f * ss;
    float sg = expf(ls);
    float fin = fmaf(eps[(size_t)b * Zsz + tid], sg, mu);
    out[(size_t)b * Zsz + tid]              = fin;
    out[((size_t)Bsz + b) * Zsz + tid]      = mu;
    out[((size_t)2 * Bsz + b) * Zsz + tid]  = sg;
}

extern "C" void kernel_launch(void* const* d_in, const int* in_sizes, int n_in,
                              void* d_out, int out_size)
{
    const float* text  = (const float*)d_in[0];
    const int*   lens  = (const int*)  d_in[1];
    const float* Wih_f = (const float*)d_in[2];
    const float* Whh_f = (const float*)d_in[3];
    const float* bih_f = (const float*)d_in[4];
    const float* bhh_f = (const float*)d_in[5];
    const float* Wih_b = (const float*)d_in[6];
    const float* Whh_b = (const float*)d_in[7];
    const float* bih_b = (const float*)d_in[8];
    const float* bhh_b = (const float*)d_in[9];
    const float* W_mu  = (const float*)d_in[10];
    const float* b_mu  = (const float*)d_in[11];
    const float* W_sig = (const float*)d_in[12];
    const float* b_sig = (const float*)d_in[13];
    const float* eps   = (const float*)d_in[14];
    float* out = (float*)d_out;

    cudaFuncSetAttribute(k_gru, cudaFuncAttributeMaxDynamicSharedMemorySize, SMEM_GRU);

    // 0) length sort + packed weight layout (one-time, cheap)
    k_sort<<<1, Bsz>>>(lens);
    {
        const size_t total = (size_t)2 * (Hsz/4) * Gsz * 4;
        k_wt4<<<(unsigned)((total + 255) / 256), 256>>>(Whh_f, Whh_b);
    }
    // 1) GI (t-major over sorted rows; dead tiles skipped)
    k_gi_gemm<<<dim3(8 * Ssz, (2 * Gsz) / 128), 256>>>(
        text, Wih_f, bih_f, Wih_b, bih_b, lens);
    // 2) Persistent GRU: 1 CTA/SM, 5-stage ring, batched epilogue
    k_gru<<<148, 288, SMEM_GRU>>>(bhh_f, bhh_b, lens);
    // 3) Average + VAE heads + reparameterized sample
    k_head<<<Bsz, 128>>>(W_mu, b_mu, W_sig, b_sig, eps, lens, out);
}